// round 1
// baseline (speedup 1.0000x reference)
#include <cuda_runtime.h>
#include <cuda_bf16.h>
#include <math.h>

// ---------------- problem constants ----------------
#define BATCH   4
#define SEQ     1024
#define DIM     1024
#define NH      16
#define NKV     4
#define HD      64
#define BLK     8
#define MROWS   (BATCH*SEQ)     // 4096
#define MODROWS (BATCH*128)     // 512

// ---------------- device scratch (no cudaMalloc allowed) ----------------
__device__ float g_SV  [MODROWS*DIM];
__device__ float g_MODA[MODROWS*3*DIM];
__device__ float g_MODF[MODROWS*3*DIM];
__device__ float g_XN  [MROWS*DIM];
__device__ float g_Q   [MROWS*DIM];
__device__ float g_Kc  [MROWS*NKV*HD];
__device__ float g_Vc  [MROWS*NKV*HD];
__device__ float g_AO  [MROWS*DIM];
__device__ float g_H   [MROWS*DIM];
__device__ float g_HN  [MROWS*DIM];
__device__ float g_F1  [MROWS*DIM];
__device__ float g_F3  [MROWS*DIM];

// ---------------- generic SGEMM: C = A(M,K) @ W(N,K)^T, fused epilogues ----------------
// EPI 0: C = acc
// EPI 1: C = acc + bias[n]
// EPI 2: C = res[m,n] + gate(m,n)*acc   gate = mod[(b*128+s/8)*3072 + 2048 + n]
template<int EPI>
__global__ __launch_bounds__(256) void sgemm_kernel(
    const float* __restrict__ A, const float* __restrict__ W, float* __restrict__ C,
    int M, int N, int K,
    const float* __restrict__ bias,
    const float* __restrict__ res,
    const float* __restrict__ mod)
{
    __shared__ __align__(16) float As[8][128];
    __shared__ __align__(16) float Bs[8][128];
    const int bm = blockIdx.y * 128;
    const int bn = blockIdx.x * 128;
    const int tid = threadIdx.x;
    const int lr = tid >> 1;           // 0..127
    const int lc = (tid & 1) << 2;     // 0 or 4
    const int tx = (tid & 15) << 3;    // 0..120
    const int ty = (tid >> 4) << 3;    // 0..120

    const float* Ap = A + (size_t)(bm + lr) * K + lc;
    const float* Wp = W + (size_t)(bn + lr) * K + lc;

    float acc[8][8];
#pragma unroll
    for (int i = 0; i < 8; i++)
#pragma unroll
        for (int j = 0; j < 8; j++) acc[i][j] = 0.f;

    for (int k0 = 0; k0 < K; k0 += 8) {
        float4 a4 = *(const float4*)(Ap + k0);
        float4 b4 = *(const float4*)(Wp + k0);
        __syncthreads();
        As[lc + 0][lr] = a4.x; As[lc + 1][lr] = a4.y;
        As[lc + 2][lr] = a4.z; As[lc + 3][lr] = a4.w;
        Bs[lc + 0][lr] = b4.x; Bs[lc + 1][lr] = b4.y;
        Bs[lc + 2][lr] = b4.z; Bs[lc + 3][lr] = b4.w;
        __syncthreads();
#pragma unroll
        for (int kk = 0; kk < 8; kk++) {
            float ar[8], br[8];
            *(float4*)&ar[0] = *(const float4*)&As[kk][ty];
            *(float4*)&ar[4] = *(const float4*)&As[kk][ty + 4];
            *(float4*)&br[0] = *(const float4*)&Bs[kk][tx];
            *(float4*)&br[4] = *(const float4*)&Bs[kk][tx + 4];
#pragma unroll
            for (int i = 0; i < 8; i++)
#pragma unroll
                for (int j = 0; j < 8; j++)
                    acc[i][j] += ar[i] * br[j];
        }
    }

#pragma unroll
    for (int i = 0; i < 8; i++) {
        const int m = bm + ty + i;
        const size_t rowoff = (size_t)m * N + bn + tx;
        if (EPI == 0) {
#pragma unroll
            for (int j = 0; j < 8; j += 4) {
                float4 v = make_float4(acc[i][j], acc[i][j+1], acc[i][j+2], acc[i][j+3]);
                *(float4*)(C + rowoff + j) = v;
            }
        } else if (EPI == 1) {
#pragma unroll
            for (int j = 0; j < 8; j++)
                C[rowoff + j] = acc[i][j] + bias[bn + tx + j];
        } else {
            const int b = m >> 10;
            const int s = m & 1023;
            const float* g = mod + (size_t)((b << 7) + (s >> 3)) * 3072 + 2048 + bn + tx;
#pragma unroll
            for (int j = 0; j < 8; j++)
                C[rowoff + j] = res[rowoff + j] + g[j] * acc[i][j];
        }
    }
}

// ---------------- pointwise kernels ----------------
__device__ __forceinline__ float siluf(float x) { return x / (1.f + __expf(-x)); }

__global__ void silu_kernel(const float* __restrict__ in, float* __restrict__ out, int n) {
    int i = blockIdx.x * blockDim.x + threadIdx.x;
    if (i < n) out[i] = siluf(in[i]);
}

__global__ void swiglu_kernel(float* __restrict__ f1, const float* __restrict__ f3, int n) {
    int i = blockIdx.x * blockDim.x + threadIdx.x;
    if (i < n) { float a = f1[i]; f1[i] = siluf(a) * f3[i]; }
}

// out[m,:] = x[m,:]*rsqrt(mean(x^2)+eps)*w[:] * (1+mod_scale) + mod_shift
__global__ __launch_bounds__(256) void rmsnorm_mod_kernel(
    const float* __restrict__ X, const float* __restrict__ w,
    const float* __restrict__ mod, float* __restrict__ out)
{
    const int m = blockIdx.x;                 // 0..4095
    const float* x = X + (size_t)m * DIM;
    const int b = m >> 10;
    const int s = m & 1023;
    const float* md = mod + (size_t)((b << 7) + (s >> 3)) * 3072;
    const int tid = threadIdx.x;

    float v[4];
    float ss = 0.f;
#pragma unroll
    for (int i = 0; i < 4; i++) { v[i] = x[tid + 256 * i]; ss += v[i] * v[i]; }
#pragma unroll
    for (int off = 16; off; off >>= 1) ss += __shfl_xor_sync(0xffffffffu, ss, off);
    __shared__ float wsum[8];
    if ((tid & 31) == 0) wsum[tid >> 5] = ss;
    __syncthreads();
    float total = wsum[0] + wsum[1] + wsum[2] + wsum[3]
                + wsum[4] + wsum[5] + wsum[6] + wsum[7];
    const float inv = rsqrtf(total * (1.f / 1024.f) + 1e-6f);
#pragma unroll
    for (int i = 0; i < 4; i++) {
        const int n = tid + 256 * i;
        out[(size_t)m * DIM + n] = v[i] * inv * w[n] * (1.f + md[1024 + n]) + md[n];
    }
}

// rope, in place. HC = row width (1024 for Q, 256 for K).
__global__ void rope_kernel(float* __restrict__ X, const float* __restrict__ fc,
                            const float* __restrict__ fs, int HC)
{
    const int hp = HC >> 1;
    const int idx = blockIdx.x * blockDim.x + threadIdx.x;
    if (idx >= MROWS * hp) return;
    const int m = idx / hp;
    const int p = idx - m * hp;     // pair index within row = h*32 + i
    const int i = p & 31;
    const int s = m & 1023;
    const float c  = fc[s * 32 + i];
    const float sn = fs[s * 32 + i];
    float* ptr = X + (size_t)m * HC + (p << 1);
    const float x1 = ptr[0], x2 = ptr[1];
    ptr[0] = x1 * c - x2 * sn;
    ptr[1] = x1 * sn + x2 * c;
}

// ---------------- flash-style fp32 attention, block-causal mask ----------------
// grid (qtile=16, head=16, batch=4), 256 threads (8 warps); warp owns 8 query rows.
__global__ __launch_bounds__(256) void attn_kernel(
    const float* __restrict__ Q, const float* __restrict__ Kt,
    const float* __restrict__ Vt, float* __restrict__ O)
{
    extern __shared__ float sm[];
    float (*Qs)[65] = (float(*)[65])(sm);
    float (*Ks)[65] = (float(*)[65])(sm + 64 * 65);
    float (*Vs)[65] = (float(*)[65])(sm + 2 * 64 * 65);
    float (*Ps)[65] = (float(*)[65])(sm + 3 * 64 * 65);

    const int qt = blockIdx.x, h = blockIdx.y, b = blockIdx.z;
    const int kvh = h >> 2;
    const int tid = threadIdx.x;
    const int warp = tid >> 5, lane = tid & 31;
    const int q0 = qt << 6;
    const int rbase = warp << 3;

    for (int i = tid; i < 4096; i += 256) {
        const int r = i >> 6, d = i & 63;
        Qs[r][d] = Q[(size_t)(b * SEQ + q0 + r) * DIM + h * HD + d] * 0.125f;
    }

    float m_i[8], l_i[8], acc0[8], acc1[8];
#pragma unroll
    for (int r = 0; r < 8; r++) { m_i[r] = -1e30f; l_i[r] = 0.f; acc0[r] = 0.f; acc1[r] = 0.f; }

    for (int t = 0; t <= qt; t++) {
        __syncthreads();
        for (int i = tid; i < 4096; i += 256) {
            const int r = i >> 6, d = i & 63;
            const size_t gi = (size_t)(b * SEQ + (t << 6) + r) * (NKV * HD) + kvh * HD + d;
            Ks[r][d] = Kt[gi];
            Vs[r][d] = Vt[gi];
        }
        __syncthreads();

        float s0[8], s1[8];
#pragma unroll
        for (int r = 0; r < 8; r++) { s0[r] = 0.f; s1[r] = 0.f; }
        for (int d = 0; d < 64; d++) {
            const float k0v = Ks[lane][d];
            const float k1v = Ks[lane + 32][d];
#pragma unroll
            for (int r = 0; r < 8; r++) {
                const float qv = Qs[rbase + r][d];
                s0[r] += qv * k0v;
                s1[r] += qv * k1v;
            }
        }
        if (t == qt) {   // diagonal tile: block-causal mask at 8-granularity
#pragma unroll
            for (int r = 0; r < 8; r++) {
                const int qb = (rbase + r) >> 3;
                if ((lane >> 3) > qb)        s0[r] = -1e30f;
                if (((lane + 32) >> 3) > qb) s1[r] = -1e30f;
            }
        }
#pragma unroll
        for (int r = 0; r < 8; r++) {
            float mx = fmaxf(s0[r], s1[r]);
#pragma unroll
            for (int off = 16; off; off >>= 1) mx = fmaxf(mx, __shfl_xor_sync(0xffffffffu, mx, off));
            const float mnew = fmaxf(m_i[r], mx);
            const float corr = __expf(m_i[r] - mnew);
            const float p0 = __expf(s0[r] - mnew);
            const float p1 = __expf(s1[r] - mnew);
            float ps = p0 + p1;
#pragma unroll
            for (int off = 16; off; off >>= 1) ps += __shfl_xor_sync(0xffffffffu, ps, off);
            l_i[r] = l_i[r] * corr + ps;
            m_i[r] = mnew;
            acc0[r] *= corr; acc1[r] *= corr;
            Ps[rbase + r][lane] = p0;
            Ps[rbase + r][lane + 32] = p1;
        }
        __syncwarp();   // Ps is produced and consumed entirely within this warp
        for (int c = 0; c < 64; c++) {
            const float v0 = Vs[c][lane];
            const float v1 = Vs[c][lane + 32];
#pragma unroll
            for (int r = 0; r < 8; r++) {
                const float p = Ps[rbase + r][c];
                acc0[r] += p * v0;
                acc1[r] += p * v1;
            }
        }
    }

#pragma unroll
    for (int r = 0; r < 8; r++) {
        const float inv = 1.f / l_i[r];
        const size_t o = (size_t)(b * SEQ + q0 + rbase + r) * DIM + h * HD;
        O[o + lane]      = acc0[r] * inv;
        O[o + lane + 32] = acc1[r] * inv;
    }
}

// ---------------- launch ----------------
extern "C" void kernel_launch(void* const* d_in, const int* in_sizes, int n_in,
                              void* d_out, int out_size)
{
    const float* x   = (const float*)d_in[0];
    const float* vec = (const float*)d_in[1];
    const float* wq  = (const float*)d_in[2];
    const float* wk  = (const float*)d_in[3];
    const float* wv  = (const float*)d_in[4];
    const float* wo  = (const float*)d_in[5];
    const float* w1  = (const float*)d_in[6];
    const float* w2  = (const float*)d_in[7];
    const float* w3  = (const float*)d_in[8];
    const float* maw = (const float*)d_in[9];
    const float* mab = (const float*)d_in[10];
    const float* mfw = (const float*)d_in[11];
    const float* mfb = (const float*)d_in[12];
    const float* n1w = (const float*)d_in[13];
    const float* n2w = (const float*)d_in[14];
    const float* fc  = (const float*)d_in[15];
    const float* fs  = (const float*)d_in[16];
    float* out = (float*)d_out;

    float *SV, *MODA, *MODF, *XN, *Qb, *Kb, *Vb, *AO, *H, *HN, *F1, *F3;
    cudaGetSymbolAddress((void**)&SV,   g_SV);
    cudaGetSymbolAddress((void**)&MODA, g_MODA);
    cudaGetSymbolAddress((void**)&MODF, g_MODF);
    cudaGetSymbolAddress((void**)&XN,   g_XN);
    cudaGetSymbolAddress((void**)&Qb,   g_Q);
    cudaGetSymbolAddress((void**)&Kb,   g_Kc);
    cudaGetSymbolAddress((void**)&Vb,   g_Vc);
    cudaGetSymbolAddress((void**)&AO,   g_AO);
    cudaGetSymbolAddress((void**)&H,    g_H);
    cudaGetSymbolAddress((void**)&HN,   g_HN);
    cudaGetSymbolAddress((void**)&F1,   g_F1);
    cudaGetSymbolAddress((void**)&F3,   g_F3);

    const int attn_smem = 4 * 64 * 65 * 4;  // 66560 B
    cudaFuncSetAttribute(attn_kernel, cudaFuncAttributeMaxDynamicSharedMemorySize, attn_smem);

    // 1) modulation: SV = silu(vec); MODA/MODF = SV @ mod_w^T + b
    silu_kernel<<<(MODROWS*DIM + 255)/256, 256>>>(vec, SV, MODROWS*DIM);
    sgemm_kernel<1><<<dim3(24, 4), 256>>>(SV, maw, MODA, MODROWS, 3*DIM, DIM, mab, nullptr, nullptr);
    sgemm_kernel<1><<<dim3(24, 4), 256>>>(SV, mfw, MODF, MODROWS, 3*DIM, DIM, mfb, nullptr, nullptr);

    // 2) xn = rmsnorm(x)*(1+scale_a)+shift_a
    rmsnorm_mod_kernel<<<MROWS, 256>>>(x, n1w, MODA, XN);

    // 3) QKV projections
    sgemm_kernel<0><<<dim3(8, 32), 256>>>(XN, wq, Qb, MROWS, DIM,     DIM, nullptr, nullptr, nullptr);
    sgemm_kernel<0><<<dim3(2, 32), 256>>>(XN, wk, Kb, MROWS, NKV*HD,  DIM, nullptr, nullptr, nullptr);
    sgemm_kernel<0><<<dim3(2, 32), 256>>>(XN, wv, Vb, MROWS, NKV*HD,  DIM, nullptr, nullptr, nullptr);

    // 4) rope on q and k
    rope_kernel<<<(MROWS*(DIM/2)    + 255)/256, 256>>>(Qb, fc, fs, DIM);
    rope_kernel<<<(MROWS*(NKV*HD/2) + 255)/256, 256>>>(Kb, fc, fs, NKV*HD);

    // 5) block-causal GQA attention
    attn_kernel<<<dim3(16, 16, 4), 256, attn_smem>>>(Qb, Kb, Vb, AO);

    // 6) h = x + gate_a * (AO @ wo^T)
    sgemm_kernel<2><<<dim3(8, 32), 256>>>(AO, wo, H, MROWS, DIM, DIM, nullptr, x, MODA);

    // 7) hn = rmsnorm(h)*(1+scale_f)+shift_f
    rmsnorm_mod_kernel<<<MROWS, 256>>>(H, n2w, MODF, HN);

    // 8) FFN: F1 = hn@w1^T, F3 = hn@w3^T, F1 = silu(F1)*F3, out = h + gate_f*(F1@w2^T)
    sgemm_kernel<0><<<dim3(8, 32), 256>>>(HN, w1, F1, MROWS, DIM, DIM, nullptr, nullptr, nullptr);
    sgemm_kernel<0><<<dim3(8, 32), 256>>>(HN, w3, F3, MROWS, DIM, DIM, nullptr, nullptr, nullptr);
    swiglu_kernel<<<(MROWS*DIM + 255)/256, 256>>>(F1, F3, MROWS*DIM);
    sgemm_kernel<2><<<dim3(8, 32), 256>>>(F1, w2, out, MROWS, DIM, DIM, nullptr, H, MODF);
}

// round 2
// speedup vs baseline: 2.2579x; 2.2579x over previous
#include <cuda_runtime.h>
#include <cuda_bf16.h>
#include <math.h>
#include <stdint.h>

// ---------------- problem constants ----------------
#define BATCH   4
#define SEQ     1024
#define DIM     1024
#define NH      16
#define NKV     4
#define HD      64
#define MROWS   (BATCH*SEQ)     // 4096
#define MODROWS (BATCH*128)     // 512

// weight split offsets (elements)
#define OFF_WQ  0
#define OFF_WK  1048576
#define OFF_WV  1310720
#define OFF_WO  1572864
#define OFF_W1  2621440
#define OFF_W2  3670016
#define OFF_W3  4718592
#define OFF_MAW 5767168
#define OFF_MFW 8912896
#define WTOTAL  12058624

// ---------------- device scratch ----------------
__device__ __nv_bfloat16 g_Whi[WTOTAL];
__device__ __nv_bfloat16 g_Wlo[WTOTAL];

__device__ __nv_bfloat16 g_SVhi[MODROWS*DIM];
__device__ __nv_bfloat16 g_SVlo[MODROWS*DIM];
__device__ __nv_bfloat16 g_XNhi[MROWS*DIM];
__device__ __nv_bfloat16 g_XNlo[MROWS*DIM];
__device__ __nv_bfloat16 g_AOhi[MROWS*DIM];
__device__ __nv_bfloat16 g_AOlo[MROWS*DIM];
__device__ __nv_bfloat16 g_HNhi[MROWS*DIM];
__device__ __nv_bfloat16 g_HNlo[MROWS*DIM];
__device__ __nv_bfloat16 g_G1hi[MROWS*DIM];
__device__ __nv_bfloat16 g_G1lo[MROWS*DIM];

__device__ float g_MODA[MODROWS*3*DIM];
__device__ float g_MODF[MODROWS*3*DIM];
__device__ float g_Q   [MROWS*DIM];
__device__ float g_Kc  [MROWS*NKV*HD];
__device__ float g_Vc  [MROWS*NKV*HD];
__device__ float g_H   [MROWS*DIM];
__device__ float g_F1  [MROWS*DIM];
__device__ float g_F3  [MROWS*DIM];

// ---------------- helpers ----------------
__device__ __forceinline__ float siluf(float x) { return x / (1.f + __expf(-x)); }

__device__ __forceinline__ void split2(float x, __nv_bfloat16& h, __nv_bfloat16& l) {
    h = __float2bfloat16(x);
    l = __float2bfloat16(x - __bfloat162float(h));
}

__device__ __forceinline__ void ldsm4(uint32_t* r, uint32_t addr) {
    asm volatile("ldmatrix.sync.aligned.m8n8.x4.shared.b16 {%0,%1,%2,%3}, [%4];"
                 : "=r"(r[0]), "=r"(r[1]), "=r"(r[2]), "=r"(r[3]) : "r"(addr));
}

__device__ __forceinline__ void mma16816(float* c, const uint32_t* a, const uint32_t* b) {
    asm volatile(
        "mma.sync.aligned.m16n8k16.row.col.f32.bf16.bf16.f32 "
        "{%0,%1,%2,%3}, {%4,%5,%6,%7}, {%8,%9}, {%0,%1,%2,%3};\n"
        : "+f"(c[0]), "+f"(c[1]), "+f"(c[2]), "+f"(c[3])
        : "r"(a[0]), "r"(a[1]), "r"(a[2]), "r"(a[3]), "r"(b[0]), "r"(b[1]));
}

// ---------------- split-bf16 tensor-core GEMM ----------------
// C(M,N) = A(M,K) @ W(N,K)^T with A,W given as bf16 hi/lo pairs.
// EPI 0: C = acc;  EPI 1: C = acc + bias[n];
// EPI 2: C = res[m,n] + gate(m,n)*acc, gate = mod[(b*128+s/8)*3072 + 2048 + n]
#define SPITCH 40   // bf16 elements per smem row (80 bytes)
template<int EPI>
__global__ __launch_bounds__(256) void hgemm_kernel(
    const __nv_bfloat16* __restrict__ Ahi, const __nv_bfloat16* __restrict__ Alo,
    const __nv_bfloat16* __restrict__ Whi, const __nv_bfloat16* __restrict__ Wlo,
    float* __restrict__ C, int M, int N, int K,
    const float* __restrict__ bias,
    const float* __restrict__ res,
    const float* __restrict__ mod)
{
    __shared__ __align__(16) __nv_bfloat16 sAh[128*SPITCH];
    __shared__ __align__(16) __nv_bfloat16 sAl[128*SPITCH];
    __shared__ __align__(16) __nv_bfloat16 sBh[128*SPITCH];
    __shared__ __align__(16) __nv_bfloat16 sBl[128*SPITCH];

    const int bm = blockIdx.y * 128;
    const int bn = blockIdx.x * 128;
    const int tid = threadIdx.x;
    const int lane = tid & 31;
    const int warp = tid >> 5;
    const int m0 = (warp >> 2) * 64;   // warp grid 2(m) x 4(n)
    const int n0 = (warp & 3) * 32;
    const int group = lane >> 2, tig = lane & 3;

    // global load mapping: k-chunk = 32 elems; 4 lanes cover one row's 64B
    const int gr = tid >> 2;          // 0..63
    const int gk = (tid & 3) * 8;     // element offset in chunk
    const size_t a0off = (size_t)(bm + gr) * K + gk;
    const size_t a1off = (size_t)(bm + 64 + gr) * K + gk;
    const size_t b0off = (size_t)(bn + gr) * K + gk;
    const size_t b1off = (size_t)(bn + 64 + gr) * K + gk;

    // smem store offsets (elements)
    const int s0 = gr * SPITCH + gk;
    const int s1 = (64 + gr) * SPITCH + gk;

    // ldmatrix lane offsets (bytes)
    const uint32_t uAh = (uint32_t)__cvta_generic_to_shared(sAh);
    const uint32_t uAl = (uint32_t)__cvta_generic_to_shared(sAl);
    const uint32_t uBh = (uint32_t)__cvta_generic_to_shared(sBh);
    const uint32_t uBl = (uint32_t)__cvta_generic_to_shared(sBl);
    const uint32_t aoffL = (uint32_t)((m0 + (lane & 7) + ((lane >> 3) & 1) * 8) * 80 + ((lane >> 4) & 1) * 16);
    const uint32_t boffL = (uint32_t)((n0 + (lane & 7) + ((lane >> 4) & 1) * 8) * 80 + ((lane >> 3) & 1) * 16);

    float c[4][4][4];
#pragma unroll
    for (int i = 0; i < 4; i++)
#pragma unroll
        for (int j = 0; j < 4; j++)
#pragma unroll
            for (int q = 0; q < 4; q++) c[i][j][q] = 0.f;

    // prefetch chunk 0
    uint4 rAh0 = *(const uint4*)(Ahi + a0off);
    uint4 rAh1 = *(const uint4*)(Ahi + a1off);
    uint4 rAl0 = *(const uint4*)(Alo + a0off);
    uint4 rAl1 = *(const uint4*)(Alo + a1off);
    uint4 rBh0 = *(const uint4*)(Whi + b0off);
    uint4 rBh1 = *(const uint4*)(Whi + b1off);
    uint4 rBl0 = *(const uint4*)(Wlo + b0off);
    uint4 rBl1 = *(const uint4*)(Wlo + b1off);

    for (int k0 = 0; k0 < K; k0 += 32) {
        __syncthreads();
        *(uint4*)&sAh[s0] = rAh0;  *(uint4*)&sAh[s1] = rAh1;
        *(uint4*)&sAl[s0] = rAl0;  *(uint4*)&sAl[s1] = rAl1;
        *(uint4*)&sBh[s0] = rBh0;  *(uint4*)&sBh[s1] = rBh1;
        *(uint4*)&sBl[s0] = rBl0;  *(uint4*)&sBl[s1] = rBl1;
        __syncthreads();

        if (k0 + 32 < K) {
            const int kn = k0 + 32;
            rAh0 = *(const uint4*)(Ahi + a0off + kn);
            rAh1 = *(const uint4*)(Ahi + a1off + kn);
            rAl0 = *(const uint4*)(Alo + a0off + kn);
            rAl1 = *(const uint4*)(Alo + a1off + kn);
            rBh0 = *(const uint4*)(Whi + b0off + kn);
            rBh1 = *(const uint4*)(Whi + b1off + kn);
            rBl0 = *(const uint4*)(Wlo + b0off + kn);
            rBl1 = *(const uint4*)(Wlo + b1off + kn);
        }

#pragma unroll
        for (int ks = 0; ks < 2; ks++) {
            uint32_t Ah[4][4], Al[4][4], Bh[4][2], Bl[4][2];
            const uint32_t ao = aoffL + ks * 32;
            const uint32_t bo = boffL + ks * 32;
#pragma unroll
            for (int mf = 0; mf < 4; mf++) {
                ldsm4(Ah[mf], uAh + ao + mf * (16 * 80));
                ldsm4(Al[mf], uAl + ao + mf * (16 * 80));
            }
#pragma unroll
            for (int p = 0; p < 2; p++) {
                uint32_t t[4];
                ldsm4(t, uBh + bo + p * (16 * 80));
                Bh[2*p][0] = t[0]; Bh[2*p][1] = t[1];
                Bh[2*p+1][0] = t[2]; Bh[2*p+1][1] = t[3];
                ldsm4(t, uBl + bo + p * (16 * 80));
                Bl[2*p][0] = t[0]; Bl[2*p][1] = t[1];
                Bl[2*p+1][0] = t[2]; Bl[2*p+1][1] = t[3];
            }
#pragma unroll
            for (int mf = 0; mf < 4; mf++) {
#pragma unroll
                for (int nf = 0; nf < 4; nf++) {
                    mma16816(c[mf][nf], Ah[mf], Bh[nf]);
                    mma16816(c[mf][nf], Ah[mf], Bl[nf]);
                    mma16816(c[mf][nf], Al[mf], Bh[nf]);
                }
            }
        }
    }

    // epilogue
#pragma unroll
    for (int mf = 0; mf < 4; mf++) {
#pragma unroll
        for (int nf = 0; nf < 4; nf++) {
            const int mA = bm + m0 + mf * 16 + group;
            const int nA = bn + n0 + nf * 8 + tig * 2;
            float* p0 = C + (size_t)mA * N + nA;
            float* p1 = C + (size_t)(mA + 8) * N + nA;
            float v0 = c[mf][nf][0], v1 = c[mf][nf][1];
            float v2 = c[mf][nf][2], v3 = c[mf][nf][3];
            if (EPI == 1) {
                const float b0v = bias[nA], b1v = bias[nA + 1];
                v0 += b0v; v1 += b1v; v2 += b0v; v3 += b1v;
            } else if (EPI == 2) {
                const int ba = mA >> 10, sa = mA & 1023;
                const float* g0 = mod + (size_t)((ba << 7) + (sa >> 3)) * 3072 + 2048;
                const int bb = (mA + 8) >> 10, sb = (mA + 8) & 1023;
                const float* g1 = mod + (size_t)((bb << 7) + (sb >> 3)) * 3072 + 2048;
                v0 = res[(size_t)mA * N + nA]       + g0[nA]     * v0;
                v1 = res[(size_t)mA * N + nA + 1]   + g0[nA + 1] * v1;
                v2 = res[(size_t)(mA+8) * N + nA]   + g1[nA]     * v2;
                v3 = res[(size_t)(mA+8) * N + nA+1] + g1[nA + 1] * v3;
            }
            *(float2*)p0 = make_float2(v0, v1);
            *(float2*)p1 = make_float2(v2, v3);
        }
    }
}

// ---------------- pointwise kernels ----------------
__global__ void wsplit_kernel(const float* __restrict__ in,
                              __nv_bfloat16* __restrict__ hi,
                              __nv_bfloat16* __restrict__ lo, int n)
{
    int i = (blockIdx.x * blockDim.x + threadIdx.x) * 4;
    if (i >= n) return;
    float4 v = *(const float4*)(in + i);
    __nv_bfloat16 h, l;
    split2(v.x, h, l); hi[i+0] = h; lo[i+0] = l;
    split2(v.y, h, l); hi[i+1] = h; lo[i+1] = l;
    split2(v.z, h, l); hi[i+2] = h; lo[i+2] = l;
    split2(v.w, h, l); hi[i+3] = h; lo[i+3] = l;
}

__global__ void silu_split_kernel(const float* __restrict__ in,
                                  __nv_bfloat16* __restrict__ hi,
                                  __nv_bfloat16* __restrict__ lo, int n)
{
    int i = blockIdx.x * blockDim.x + threadIdx.x;
    if (i >= n) return;
    __nv_bfloat16 h, l;
    split2(siluf(in[i]), h, l);
    hi[i] = h; lo[i] = l;
}

__global__ void swiglu_split_kernel(const float* __restrict__ f1, const float* __restrict__ f3,
                                    __nv_bfloat16* __restrict__ hi,
                                    __nv_bfloat16* __restrict__ lo, int n)
{
    int i = blockIdx.x * blockDim.x + threadIdx.x;
    if (i >= n) return;
    __nv_bfloat16 h, l;
    split2(siluf(f1[i]) * f3[i], h, l);
    hi[i] = h; lo[i] = l;
}

// hi/lo(out) = rmsnorm(x)*w*(1+mod_scale)+mod_shift
__global__ __launch_bounds__(256) void rmsnorm_mod_split_kernel(
    const float* __restrict__ X, const float* __restrict__ w,
    const float* __restrict__ mod,
    __nv_bfloat16* __restrict__ hi, __nv_bfloat16* __restrict__ lo)
{
    const int m = blockIdx.x;
    const float* x = X + (size_t)m * DIM;
    const int b = m >> 10;
    const int s = m & 1023;
    const float* md = mod + (size_t)((b << 7) + (s >> 3)) * 3072;
    const int tid = threadIdx.x;

    float v[4];
    float ss = 0.f;
#pragma unroll
    for (int i = 0; i < 4; i++) { v[i] = x[tid + 256 * i]; ss += v[i] * v[i]; }
#pragma unroll
    for (int off = 16; off; off >>= 1) ss += __shfl_xor_sync(0xffffffffu, ss, off);
    __shared__ float wsum[8];
    if ((tid & 31) == 0) wsum[tid >> 5] = ss;
    __syncthreads();
    float total = wsum[0] + wsum[1] + wsum[2] + wsum[3]
                + wsum[4] + wsum[5] + wsum[6] + wsum[7];
    const float inv = rsqrtf(total * (1.f / 1024.f) + 1e-6f);
#pragma unroll
    for (int i = 0; i < 4; i++) {
        const int n = tid + 256 * i;
        float y = v[i] * inv * w[n] * (1.f + md[1024 + n]) + md[n];
        __nv_bfloat16 h, l;
        split2(y, h, l);
        hi[(size_t)m * DIM + n] = h;
        lo[(size_t)m * DIM + n] = l;
    }
}

// rope, in place (fp32). HC = row width (1024 for Q, 256 for K).
__global__ void rope_kernel(float* __restrict__ X, const float* __restrict__ fc,
                            const float* __restrict__ fs, int HC)
{
    const int hp = HC >> 1;
    const int idx = blockIdx.x * blockDim.x + threadIdx.x;
    if (idx >= MROWS * hp) return;
    const int m = idx / hp;
    const int p = idx - m * hp;
    const int i = p & 31;
    const int s = m & 1023;
    const float cc = fc[s * 32 + i];
    const float sn = fs[s * 32 + i];
    float* ptr = X + (size_t)m * HC + (p << 1);
    const float x1 = ptr[0], x2 = ptr[1];
    ptr[0] = x1 * cc - x2 * sn;
    ptr[1] = x1 * sn + x2 * cc;
}

// ---------------- flash-style fp32 attention, block-causal mask ----------------
__global__ __launch_bounds__(256) void attn_kernel(
    const float* __restrict__ Q, const float* __restrict__ Kt,
    const float* __restrict__ Vt,
    __nv_bfloat16* __restrict__ Ohi, __nv_bfloat16* __restrict__ Olo)
{
    extern __shared__ float sm[];
    float (*Qs)[65] = (float(*)[65])(sm);
    float (*Ks)[65] = (float(*)[65])(sm + 64 * 65);
    float (*Vs)[65] = (float(*)[65])(sm + 2 * 64 * 65);
    float (*Ps)[65] = (float(*)[65])(sm + 3 * 64 * 65);

    const int qt = blockIdx.x, h = blockIdx.y, b = blockIdx.z;
    const int kvh = h >> 2;
    const int tid = threadIdx.x;
    const int warp = tid >> 5, lane = tid & 31;
    const int q0 = qt << 6;
    const int rbase = warp << 3;

    for (int i = tid; i < 4096; i += 256) {
        const int r = i >> 6, d = i & 63;
        Qs[r][d] = Q[(size_t)(b * SEQ + q0 + r) * DIM + h * HD + d] * 0.125f;
    }

    float m_i[8], l_i[8], acc0[8], acc1[8];
#pragma unroll
    for (int r = 0; r < 8; r++) { m_i[r] = -1e30f; l_i[r] = 0.f; acc0[r] = 0.f; acc1[r] = 0.f; }

    for (int t = 0; t <= qt; t++) {
        __syncthreads();
        for (int i = tid; i < 4096; i += 256) {
            const int r = i >> 6, d = i & 63;
            const size_t gi = (size_t)(b * SEQ + (t << 6) + r) * (NKV * HD) + kvh * HD + d;
            Ks[r][d] = Kt[gi];
            Vs[r][d] = Vt[gi];
        }
        __syncthreads();

        float s0[8], s1[8];
#pragma unroll
        for (int r = 0; r < 8; r++) { s0[r] = 0.f; s1[r] = 0.f; }
        for (int d = 0; d < 64; d++) {
            const float k0v = Ks[lane][d];
            const float k1v = Ks[lane + 32][d];
#pragma unroll
            for (int r = 0; r < 8; r++) {
                const float qv = Qs[rbase + r][d];
                s0[r] += qv * k0v;
                s1[r] += qv * k1v;
            }
        }
        if (t == qt) {
#pragma unroll
            for (int r = 0; r < 8; r++) {
                const int qb = (rbase + r) >> 3;
                if ((lane >> 3) > qb)        s0[r] = -1e30f;
                if (((lane + 32) >> 3) > qb) s1[r] = -1e30f;
            }
        }
#pragma unroll
        for (int r = 0; r < 8; r++) {
            float mx = fmaxf(s0[r], s1[r]);
#pragma unroll
            for (int off = 16; off; off >>= 1) mx = fmaxf(mx, __shfl_xor_sync(0xffffffffu, mx, off));
            const float mnew = fmaxf(m_i[r], mx);
            const float corr = __expf(m_i[r] - mnew);
            const float p0 = __expf(s0[r] - mnew);
            const float p1 = __expf(s1[r] - mnew);
            float ps = p0 + p1;
#pragma unroll
            for (int off = 16; off; off >>= 1) ps += __shfl_xor_sync(0xffffffffu, ps, off);
            l_i[r] = l_i[r] * corr + ps;
            m_i[r] = mnew;
            acc0[r] *= corr; acc1[r] *= corr;
            Ps[rbase + r][lane] = p0;
            Ps[rbase + r][lane + 32] = p1;
        }
        __syncwarp();
        for (int cidx = 0; cidx < 64; cidx++) {
            const float v0 = Vs[cidx][lane];
            const float v1 = Vs[cidx][lane + 32];
#pragma unroll
            for (int r = 0; r < 8; r++) {
                const float p = Ps[rbase + r][cidx];
                acc0[r] += p * v0;
                acc1[r] += p * v1;
            }
        }
    }

#pragma unroll
    for (int r = 0; r < 8; r++) {
        const float inv = 1.f / l_i[r];
        const size_t o = (size_t)(b * SEQ + q0 + rbase + r) * DIM + h * HD;
        __nv_bfloat16 h0, l0, h1, l1;
        split2(acc0[r] * inv, h0, l0);
        split2(acc1[r] * inv, h1, l1);
        Ohi[o + lane] = h0;      Olo[o + lane] = l0;
        Ohi[o + lane + 32] = h1; Olo[o + lane + 32] = l1;
    }
}

// ---------------- launch ----------------
extern "C" void kernel_launch(void* const* d_in, const int* in_sizes, int n_in,
                              void* d_out, int out_size)
{
    const float* x   = (const float*)d_in[0];
    const float* vec = (const float*)d_in[1];
    const float* wq  = (const float*)d_in[2];
    const float* wk  = (const float*)d_in[3];
    const float* wv  = (const float*)d_in[4];
    const float* wo  = (const float*)d_in[5];
    const float* w1  = (const float*)d_in[6];
    const float* w2  = (const float*)d_in[7];
    const float* w3  = (const float*)d_in[8];
    const float* maw = (const float*)d_in[9];
    const float* mab = (const float*)d_in[10];
    const float* mfw = (const float*)d_in[11];
    const float* mfb = (const float*)d_in[12];
    const float* n1w = (const float*)d_in[13];
    const float* n2w = (const float*)d_in[14];
    const float* fc  = (const float*)d_in[15];
    const float* fs  = (const float*)d_in[16];
    float* out = (float*)d_out;

    __nv_bfloat16 *Whi, *Wlo, *SVhi, *SVlo, *XNhi, *XNlo, *AOhi, *AOlo, *HNhi, *HNlo, *G1hi, *G1lo;
    float *MODA, *MODF, *Qb, *Kb, *Vb, *H, *F1, *F3;
    cudaGetSymbolAddress((void**)&Whi,  g_Whi);
    cudaGetSymbolAddress((void**)&Wlo,  g_Wlo);
    cudaGetSymbolAddress((void**)&SVhi, g_SVhi);
    cudaGetSymbolAddress((void**)&SVlo, g_SVlo);
    cudaGetSymbolAddress((void**)&XNhi, g_XNhi);
    cudaGetSymbolAddress((void**)&XNlo, g_XNlo);
    cudaGetSymbolAddress((void**)&AOhi, g_AOhi);
    cudaGetSymbolAddress((void**)&AOlo, g_AOlo);
    cudaGetSymbolAddress((void**)&HNhi, g_HNhi);
    cudaGetSymbolAddress((void**)&HNlo, g_HNlo);
    cudaGetSymbolAddress((void**)&G1hi, g_G1hi);
    cudaGetSymbolAddress((void**)&G1lo, g_G1lo);
    cudaGetSymbolAddress((void**)&MODA, g_MODA);
    cudaGetSymbolAddress((void**)&MODF, g_MODF);
    cudaGetSymbolAddress((void**)&Qb,   g_Q);
    cudaGetSymbolAddress((void**)&Kb,   g_Kc);
    cudaGetSymbolAddress((void**)&Vb,   g_Vc);
    cudaGetSymbolAddress((void**)&H,    g_H);
    cudaGetSymbolAddress((void**)&F1,   g_F1);
    cudaGetSymbolAddress((void**)&F3,   g_F3);

    const int attn_smem = 4 * 64 * 65 * 4;
    cudaFuncSetAttribute(attn_kernel, cudaFuncAttributeMaxDynamicSharedMemorySize, attn_smem);

    // 0) split all weights to bf16 hi/lo
    auto wlaunch = [&](const float* src, int off, int cnt) {
        wsplit_kernel<<<(cnt/4 + 255)/256, 256>>>(src, Whi + off, Wlo + off, cnt);
    };
    wlaunch(wq,  OFF_WQ,  1048576);
    wlaunch(wk,  OFF_WK,  262144);
    wlaunch(wv,  OFF_WV,  262144);
    wlaunch(wo,  OFF_WO,  1048576);
    wlaunch(w1,  OFF_W1,  1048576);
    wlaunch(w2,  OFF_W2,  1048576);
    wlaunch(w3,  OFF_W3,  1048576);
    wlaunch(maw, OFF_MAW, 3145728);
    wlaunch(mfw, OFF_MFW, 3145728);

    // 1) modulation
    silu_split_kernel<<<(MODROWS*DIM + 255)/256, 256>>>(vec, SVhi, SVlo, MODROWS*DIM);
    hgemm_kernel<1><<<dim3(24, 4), 256>>>(SVhi, SVlo, Whi+OFF_MAW, Wlo+OFF_MAW, MODA,
                                          MODROWS, 3*DIM, DIM, mab, nullptr, nullptr);
    hgemm_kernel<1><<<dim3(24, 4), 256>>>(SVhi, SVlo, Whi+OFF_MFW, Wlo+OFF_MFW, MODF,
                                          MODROWS, 3*DIM, DIM, mfb, nullptr, nullptr);

    // 2) xn = rmsnorm(x)*(1+scale_a)+shift_a  -> bf16 hi/lo
    rmsnorm_mod_split_kernel<<<MROWS, 256>>>(x, n1w, MODA, XNhi, XNlo);

    // 3) QKV projections (fp32 out)
    hgemm_kernel<0><<<dim3(8, 32), 256>>>(XNhi, XNlo, Whi+OFF_WQ, Wlo+OFF_WQ, Qb,
                                          MROWS, DIM, DIM, nullptr, nullptr, nullptr);
    hgemm_kernel<0><<<dim3(2, 32), 256>>>(XNhi, XNlo, Whi+OFF_WK, Wlo+OFF_WK, Kb,
                                          MROWS, NKV*HD, DIM, nullptr, nullptr, nullptr);
    hgemm_kernel<0><<<dim3(2, 32), 256>>>(XNhi, XNlo, Whi+OFF_WV, Wlo+OFF_WV, Vb,
                                          MROWS, NKV*HD, DIM, nullptr, nullptr, nullptr);

    // 4) rope
    rope_kernel<<<(MROWS*(DIM/2)    + 255)/256, 256>>>(Qb, fc, fs, DIM);
    rope_kernel<<<(MROWS*(NKV*HD/2) + 255)/256, 256>>>(Kb, fc, fs, NKV*HD);

    // 5) attention -> AO bf16 hi/lo
    attn_kernel<<<dim3(16, 16, 4), 256, attn_smem>>>(Qb, Kb, Vb, AOhi, AOlo);

    // 6) h = x + gate_a * (AO @ wo^T)
    hgemm_kernel<2><<<dim3(8, 32), 256>>>(AOhi, AOlo, Whi+OFF_WO, Wlo+OFF_WO, H,
                                          MROWS, DIM, DIM, nullptr, x, MODA);

    // 7) hn
    rmsnorm_mod_split_kernel<<<MROWS, 256>>>(H, n2w, MODF, HNhi, HNlo);

    // 8) FFN
    hgemm_kernel<0><<<dim3(8, 32), 256>>>(HNhi, HNlo, Whi+OFF_W1, Wlo+OFF_W1, F1,
                                          MROWS, DIM, DIM, nullptr, nullptr, nullptr);
    hgemm_kernel<0><<<dim3(8, 32), 256>>>(HNhi, HNlo, Whi+OFF_W3, Wlo+OFF_W3, F3,
                                          MROWS, DIM, DIM, nullptr, nullptr, nullptr);
    swiglu_split_kernel<<<(MROWS*DIM + 255)/256, 256>>>(F1, F3, G1hi, G1lo, MROWS*DIM);
    hgemm_kernel<2><<<dim3(8, 32), 256>>>(G1hi, G1lo, Whi+OFF_W2, Wlo+OFF_W2, out,
                                          MROWS, DIM, DIM, nullptr, H, MODF);
}

// round 3
// speedup vs baseline: 2.8626x; 1.2678x over previous
#include <cuda_runtime.h>
#include <cuda_bf16.h>
#include <math.h>
#include <stdint.h>

// ---------------- problem constants ----------------
#define BATCH   4
#define SEQ     1024
#define DIM     1024
#define NH      16
#define NKV     4
#define HD      64
#define MROWS   (BATCH*SEQ)     // 4096
#define MODROWS (BATCH*128)     // 512

// weight split offsets (elements)
#define OFF_WQ  0
#define OFF_WK  1048576
#define OFF_WV  1310720
#define OFF_WO  1572864
#define OFF_W1  2621440
#define OFF_W2  3670016
#define OFF_W3  4718592
#define OFF_MAW 5767168
#define OFF_MFW 8912896
#define WTOTAL  12058624

// ---------------- device scratch ----------------
__device__ __nv_bfloat16 g_Whi[WTOTAL];
__device__ __nv_bfloat16 g_Wlo[WTOTAL];

__device__ __nv_bfloat16 g_SVhi[MODROWS*DIM];
__device__ __nv_bfloat16 g_SVlo[MODROWS*DIM];
__device__ __nv_bfloat16 g_XNhi[MROWS*DIM];
__device__ __nv_bfloat16 g_XNlo[MROWS*DIM];
__device__ __nv_bfloat16 g_AOhi[MROWS*DIM];
__device__ __nv_bfloat16 g_AOlo[MROWS*DIM];
__device__ __nv_bfloat16 g_HNhi[MROWS*DIM];
__device__ __nv_bfloat16 g_HNlo[MROWS*DIM];
__device__ __nv_bfloat16 g_G1hi[MROWS*DIM];
__device__ __nv_bfloat16 g_G1lo[MROWS*DIM];

__device__ float g_MODA[MODROWS*3*DIM];
__device__ float g_MODF[MODROWS*3*DIM];
__device__ float g_Q   [MROWS*DIM];
__device__ float g_Kc  [MROWS*NKV*HD];
__device__ float g_Vc  [MROWS*NKV*HD];
__device__ float g_H   [MROWS*DIM];
__device__ float g_F1  [MROWS*DIM];
__device__ float g_F3  [MROWS*DIM];

// ---------------- helpers ----------------
__device__ __forceinline__ float siluf(float x) { return x / (1.f + __expf(-x)); }

__device__ __forceinline__ void split2(float x, __nv_bfloat16& h, __nv_bfloat16& l) {
    h = __float2bfloat16(x);
    l = __float2bfloat16(x - __bfloat162float(h));
}

__device__ __forceinline__ void split_pack2(float x0, float x1, uint32_t& hi, uint32_t& lo) {
    __nv_bfloat16 h0 = __float2bfloat16(x0);
    __nv_bfloat16 h1 = __float2bfloat16(x1);
    __nv_bfloat16 l0 = __float2bfloat16(x0 - __bfloat162float(h0));
    __nv_bfloat16 l1 = __float2bfloat16(x1 - __bfloat162float(h1));
    hi = ((uint32_t)__bfloat16_as_ushort(h1) << 16) | __bfloat16_as_ushort(h0);
    lo = ((uint32_t)__bfloat16_as_ushort(l1) << 16) | __bfloat16_as_ushort(l0);
}

__device__ __forceinline__ void ldsm4(uint32_t* r, uint32_t addr) {
    asm volatile("ldmatrix.sync.aligned.m8n8.x4.shared.b16 {%0,%1,%2,%3}, [%4];"
                 : "=r"(r[0]), "=r"(r[1]), "=r"(r[2]), "=r"(r[3]) : "r"(addr));
}

__device__ __forceinline__ void ldsm4t(uint32_t* r, uint32_t addr) {
    asm volatile("ldmatrix.sync.aligned.m8n8.x4.trans.shared.b16 {%0,%1,%2,%3}, [%4];"
                 : "=r"(r[0]), "=r"(r[1]), "=r"(r[2]), "=r"(r[3]) : "r"(addr));
}

__device__ __forceinline__ void mma16816(float* c, const uint32_t* a, const uint32_t* b) {
    asm volatile(
        "mma.sync.aligned.m16n8k16.row.col.f32.bf16.bf16.f32 "
        "{%0,%1,%2,%3}, {%4,%5,%6,%7}, {%8,%9}, {%0,%1,%2,%3};\n"
        : "+f"(c[0]), "+f"(c[1]), "+f"(c[2]), "+f"(c[3])
        : "r"(a[0]), "r"(a[1]), "r"(a[2]), "r"(a[3]), "r"(b[0]), "r"(b[1]));
}

// ---------------- split-bf16 tensor-core GEMM ----------------
#define SPITCH 40   // bf16 elements per smem row (80 bytes)
template<int EPI>
__global__ __launch_bounds__(256) void hgemm_kernel(
    const __nv_bfloat16* __restrict__ Ahi, const __nv_bfloat16* __restrict__ Alo,
    const __nv_bfloat16* __restrict__ Whi, const __nv_bfloat16* __restrict__ Wlo,
    float* __restrict__ C, int M, int N, int K,
    const float* __restrict__ bias,
    const float* __restrict__ res,
    const float* __restrict__ mod)
{
    __shared__ __align__(16) __nv_bfloat16 sAh[128*SPITCH];
    __shared__ __align__(16) __nv_bfloat16 sAl[128*SPITCH];
    __shared__ __align__(16) __nv_bfloat16 sBh[128*SPITCH];
    __shared__ __align__(16) __nv_bfloat16 sBl[128*SPITCH];

    const int bm = blockIdx.y * 128;
    const int bn = blockIdx.x * 128;
    const int tid = threadIdx.x;
    const int lane = tid & 31;
    const int warp = tid >> 5;
    const int m0 = (warp >> 2) * 64;
    const int n0 = (warp & 3) * 32;
    const int group = lane >> 2, tig = lane & 3;

    const int gr = tid >> 2;
    const int gk = (tid & 3) * 8;
    const size_t a0off = (size_t)(bm + gr) * K + gk;
    const size_t a1off = (size_t)(bm + 64 + gr) * K + gk;
    const size_t b0off = (size_t)(bn + gr) * K + gk;
    const size_t b1off = (size_t)(bn + 64 + gr) * K + gk;

    const int s0 = gr * SPITCH + gk;
    const int s1 = (64 + gr) * SPITCH + gk;

    const uint32_t uAh = (uint32_t)__cvta_generic_to_shared(sAh);
    const uint32_t uAl = (uint32_t)__cvta_generic_to_shared(sAl);
    const uint32_t uBh = (uint32_t)__cvta_generic_to_shared(sBh);
    const uint32_t uBl = (uint32_t)__cvta_generic_to_shared(sBl);
    const uint32_t aoffL = (uint32_t)((m0 + (lane & 7) + ((lane >> 3) & 1) * 8) * 80 + ((lane >> 4) & 1) * 16);
    const uint32_t boffL = (uint32_t)((n0 + (lane & 7) + ((lane >> 4) & 1) * 8) * 80 + ((lane >> 3) & 1) * 16);

    float c[4][4][4];
#pragma unroll
    for (int i = 0; i < 4; i++)
#pragma unroll
        for (int j = 0; j < 4; j++)
#pragma unroll
            for (int q = 0; q < 4; q++) c[i][j][q] = 0.f;

    uint4 rAh0 = *(const uint4*)(Ahi + a0off);
    uint4 rAh1 = *(const uint4*)(Ahi + a1off);
    uint4 rAl0 = *(const uint4*)(Alo + a0off);
    uint4 rAl1 = *(const uint4*)(Alo + a1off);
    uint4 rBh0 = *(const uint4*)(Whi + b0off);
    uint4 rBh1 = *(const uint4*)(Whi + b1off);
    uint4 rBl0 = *(const uint4*)(Wlo + b0off);
    uint4 rBl1 = *(const uint4*)(Wlo + b1off);

    for (int k0 = 0; k0 < K; k0 += 32) {
        __syncthreads();
        *(uint4*)&sAh[s0] = rAh0;  *(uint4*)&sAh[s1] = rAh1;
        *(uint4*)&sAl[s0] = rAl0;  *(uint4*)&sAl[s1] = rAl1;
        *(uint4*)&sBh[s0] = rBh0;  *(uint4*)&sBh[s1] = rBh1;
        *(uint4*)&sBl[s0] = rBl0;  *(uint4*)&sBl[s1] = rBl1;
        __syncthreads();

        if (k0 + 32 < K) {
            const int kn = k0 + 32;
            rAh0 = *(const uint4*)(Ahi + a0off + kn);
            rAh1 = *(const uint4*)(Ahi + a1off + kn);
            rAl0 = *(const uint4*)(Alo + a0off + kn);
            rAl1 = *(const uint4*)(Alo + a1off + kn);
            rBh0 = *(const uint4*)(Whi + b0off + kn);
            rBh1 = *(const uint4*)(Whi + b1off + kn);
            rBl0 = *(const uint4*)(Wlo + b0off + kn);
            rBl1 = *(const uint4*)(Wlo + b1off + kn);
        }

#pragma unroll
        for (int ks = 0; ks < 2; ks++) {
            uint32_t Ah[4][4], Al[4][4], Bh[4][2], Bl[4][2];
            const uint32_t ao = aoffL + ks * 32;
            const uint32_t bo = boffL + ks * 32;
#pragma unroll
            for (int mf = 0; mf < 4; mf++) {
                ldsm4(Ah[mf], uAh + ao + mf * (16 * 80));
                ldsm4(Al[mf], uAl + ao + mf * (16 * 80));
            }
#pragma unroll
            for (int p = 0; p < 2; p++) {
                uint32_t t[4];
                ldsm4(t, uBh + bo + p * (16 * 80));
                Bh[2*p][0] = t[0]; Bh[2*p][1] = t[1];
                Bh[2*p+1][0] = t[2]; Bh[2*p+1][1] = t[3];
                ldsm4(t, uBl + bo + p * (16 * 80));
                Bl[2*p][0] = t[0]; Bl[2*p][1] = t[1];
                Bl[2*p+1][0] = t[2]; Bl[2*p+1][1] = t[3];
            }
#pragma unroll
            for (int mf = 0; mf < 4; mf++) {
#pragma unroll
                for (int nf = 0; nf < 4; nf++) {
                    mma16816(c[mf][nf], Ah[mf], Bh[nf]);
                    mma16816(c[mf][nf], Ah[mf], Bl[nf]);
                    mma16816(c[mf][nf], Al[mf], Bh[nf]);
                }
            }
        }
    }

#pragma unroll
    for (int mf = 0; mf < 4; mf++) {
#pragma unroll
        for (int nf = 0; nf < 4; nf++) {
            const int mA = bm + m0 + mf * 16 + group;
            const int nA = bn + n0 + nf * 8 + tig * 2;
            float* p0 = C + (size_t)mA * N + nA;
            float* p1 = C + (size_t)(mA + 8) * N + nA;
            float v0 = c[mf][nf][0], v1 = c[mf][nf][1];
            float v2 = c[mf][nf][2], v3 = c[mf][nf][3];
            if (EPI == 1) {
                const float b0v = bias[nA], b1v = bias[nA + 1];
                v0 += b0v; v1 += b1v; v2 += b0v; v3 += b1v;
            } else if (EPI == 2) {
                const int ba = mA >> 10, sa = mA & 1023;
                const float* g0 = mod + (size_t)((ba << 7) + (sa >> 3)) * 3072 + 2048;
                const int bb = (mA + 8) >> 10, sb = (mA + 8) & 1023;
                const float* g1 = mod + (size_t)((bb << 7) + (sb >> 3)) * 3072 + 2048;
                v0 = res[(size_t)mA * N + nA]       + g0[nA]     * v0;
                v1 = res[(size_t)mA * N + nA + 1]   + g0[nA + 1] * v1;
                v2 = res[(size_t)(mA+8) * N + nA]   + g1[nA]     * v2;
                v3 = res[(size_t)(mA+8) * N + nA+1] + g1[nA + 1] * v3;
            }
            *(float2*)p0 = make_float2(v0, v1);
            *(float2*)p1 = make_float2(v2, v3);
        }
    }
}

// ---------------- merged weight split ----------------
struct WSegs {
    const float* src[9];
    int off[10];
};

__global__ __launch_bounds__(256) void wsplit_all_kernel(
    WSegs ws, __nv_bfloat16* __restrict__ hi, __nv_bfloat16* __restrict__ lo)
{
    const int base = blockIdx.x * 1024 + threadIdx.x * 4;
    int seg = 0;
#pragma unroll
    for (int k = 1; k < 9; k++) if (base >= ws.off[k]) seg = k;
    const float* src = ws.src[seg] + (base - ws.off[seg]);
    float4 v = *(const float4*)src;
    uint32_t h01, l01, h23, l23;
    split_pack2(v.x, v.y, h01, l01);
    split_pack2(v.z, v.w, h23, l23);
    *(uint2*)(hi + base) = make_uint2(h01, h23);
    *(uint2*)(lo + base) = make_uint2(l01, l23);
}

// ---------------- pointwise kernels ----------------
__global__ void silu_split_kernel(const float* __restrict__ in,
                                  __nv_bfloat16* __restrict__ hi,
                                  __nv_bfloat16* __restrict__ lo, int n)
{
    int i = blockIdx.x * blockDim.x + threadIdx.x;
    if (i >= n) return;
    __nv_bfloat16 h, l;
    split2(siluf(in[i]), h, l);
    hi[i] = h; lo[i] = l;
}

__global__ void swiglu_split_kernel(const float* __restrict__ f1, const float* __restrict__ f3,
                                    __nv_bfloat16* __restrict__ hi,
                                    __nv_bfloat16* __restrict__ lo, int n)
{
    int i = blockIdx.x * blockDim.x + threadIdx.x;
    if (i >= n) return;
    __nv_bfloat16 h, l;
    split2(siluf(f1[i]) * f3[i], h, l);
    hi[i] = h; lo[i] = l;
}

__global__ __launch_bounds__(256) void rmsnorm_mod_split_kernel(
    const float* __restrict__ X, const float* __restrict__ w,
    const float* __restrict__ mod,
    __nv_bfloat16* __restrict__ hi, __nv_bfloat16* __restrict__ lo)
{
    const int m = blockIdx.x;
    const float* x = X + (size_t)m * DIM;
    const int b = m >> 10;
    const int s = m & 1023;
    const float* md = mod + (size_t)((b << 7) + (s >> 3)) * 3072;
    const int tid = threadIdx.x;

    float v[4];
    float ss = 0.f;
#pragma unroll
    for (int i = 0; i < 4; i++) { v[i] = x[tid + 256 * i]; ss += v[i] * v[i]; }
#pragma unroll
    for (int off = 16; off; off >>= 1) ss += __shfl_xor_sync(0xffffffffu, ss, off);
    __shared__ float wsum[8];
    if ((tid & 31) == 0) wsum[tid >> 5] = ss;
    __syncthreads();
    float total = wsum[0] + wsum[1] + wsum[2] + wsum[3]
                + wsum[4] + wsum[5] + wsum[6] + wsum[7];
    const float inv = rsqrtf(total * (1.f / 1024.f) + 1e-6f);
#pragma unroll
    for (int i = 0; i < 4; i++) {
        const int n = tid + 256 * i;
        float y = v[i] * inv * w[n] * (1.f + md[1024 + n]) + md[n];
        __nv_bfloat16 h, l;
        split2(y, h, l);
        hi[(size_t)m * DIM + n] = h;
        lo[(size_t)m * DIM + n] = l;
    }
}

__global__ void rope_kernel(float* __restrict__ X, const float* __restrict__ fc,
                            const float* __restrict__ fs, int HC)
{
    const int hp = HC >> 1;
    const int idx = blockIdx.x * blockDim.x + threadIdx.x;
    if (idx >= MROWS * hp) return;
    const int m = idx / hp;
    const int p = idx - m * hp;
    const int i = p & 31;
    const int s = m & 1023;
    const float cc = fc[s * 32 + i];
    const float sn = fs[s * 32 + i];
    float* ptr = X + (size_t)m * HC + (p << 1);
    const float x1 = ptr[0], x2 = ptr[1];
    ptr[0] = x1 * cc - x2 * sn;
    ptr[1] = x1 * sn + x2 * cc;
}

// ---------------- tensor-core split-bf16 flash attention ----------------
// grid (qtile=16, head=16, batch=4), 128 threads (4 warps), warp = 16 q rows.
#define APITCH 72
__global__ __launch_bounds__(128) void attn_tc_kernel(
    const float* __restrict__ Q, const float* __restrict__ Kt,
    const float* __restrict__ Vt,
    __nv_bfloat16* __restrict__ Ohi, __nv_bfloat16* __restrict__ Olo)
{
    extern __shared__ __align__(16) __nv_bfloat16 sb[];
    __nv_bfloat16* Qh = sb;
    __nv_bfloat16* Ql = sb + 4608;
    __nv_bfloat16* Kh = sb + 9216;
    __nv_bfloat16* Kl = sb + 13824;
    __nv_bfloat16* Vh = sb + 18432;
    __nv_bfloat16* Vl = sb + 23040;

    const int qt = blockIdx.x, h = blockIdx.y, b = blockIdx.z;
    const int kvh = h >> 2;
    const int tid = threadIdx.x, warp = tid >> 5, lane = tid & 31;
    const int q0 = qt << 6;

    // load + scale + split Q tile (64x64)
    for (int i = tid; i < 1024; i += 128) {
        const int r = i >> 4;
        const int c4 = (i & 15) << 2;
        float4 v = *(const float4*)(Q + (size_t)(b * SEQ + q0 + r) * DIM + h * HD + c4);
        v.x *= 0.125f; v.y *= 0.125f; v.z *= 0.125f; v.w *= 0.125f;
        uint32_t h01, l01, h23, l23;
        split_pack2(v.x, v.y, h01, l01);
        split_pack2(v.z, v.w, h23, l23);
        *(uint2*)(Qh + r * APITCH + c4) = make_uint2(h01, h23);
        *(uint2*)(Ql + r * APITCH + c4) = make_uint2(l01, l23);
    }
    __syncthreads();

    // Q fragments in registers
    const uint32_t uQh = (uint32_t)__cvta_generic_to_shared(Qh);
    const uint32_t uQl = (uint32_t)__cvta_generic_to_shared(Ql);
    uint32_t qh[4][4], ql[4][4];
    {
        const int qrow = warp * 16 + (lane & 15);
#pragma unroll
        for (int k = 0; k < 4; k++) {
            const uint32_t a = (uint32_t)((qrow * APITCH + k * 16 + (lane >> 4) * 8) * 2);
            ldsm4(qh[k], uQh + a);
            ldsm4(ql[k], uQl + a);
        }
    }

    const uint32_t uKh = (uint32_t)__cvta_generic_to_shared(Kh);
    const uint32_t uKl = (uint32_t)__cvta_generic_to_shared(Kl);
    const uint32_t uVh = (uint32_t)__cvta_generic_to_shared(Vh);
    const uint32_t uVl = (uint32_t)__cvta_generic_to_shared(Vl);
    const int krow = (lane & 7) + ((lane >> 4) & 1) * 8;
    const int kcol = ((lane >> 3) & 1) * 8;
    const int vrow = (lane & 7) + ((lane >> 3) & 1) * 8;
    const int vcol = ((lane >> 4) & 1) * 8;

    float o[8][4];
#pragma unroll
    for (int j = 0; j < 8; j++)
#pragma unroll
        for (int q = 0; q < 4; q++) o[j][q] = 0.f;
    float m0 = -1e30f, m1 = -1e30f, l0 = 0.f, l1 = 0.f;

    for (int t = 0; t <= qt; t++) {
        __syncthreads();
        for (int i = tid; i < 1024; i += 128) {
            const int r = i >> 4;
            const int c4 = (i & 15) << 2;
            const size_t g = (size_t)(b * SEQ + t * 64 + r) * (NKV * HD) + kvh * HD + c4;
            float4 kv = *(const float4*)(Kt + g);
            uint32_t h01, l01, h23, l23;
            split_pack2(kv.x, kv.y, h01, l01);
            split_pack2(kv.z, kv.w, h23, l23);
            *(uint2*)(Kh + r * APITCH + c4) = make_uint2(h01, h23);
            *(uint2*)(Kl + r * APITCH + c4) = make_uint2(l01, l23);
            float4 vv = *(const float4*)(Vt + g);
            split_pack2(vv.x, vv.y, h01, l01);
            split_pack2(vv.z, vv.w, h23, l23);
            *(uint2*)(Vh + r * APITCH + c4) = make_uint2(h01, h23);
            *(uint2*)(Vl + r * APITCH + c4) = make_uint2(l01, l23);
        }
        __syncthreads();

        // S = Q @ K^T  (3-product split)
        float s[8][4];
#pragma unroll
        for (int j = 0; j < 8; j++)
#pragma unroll
            for (int q = 0; q < 4; q++) s[j][q] = 0.f;
#pragma unroll
        for (int k = 0; k < 4; k++) {
            uint32_t bh[4][4], bl[4][4];
#pragma unroll
            for (int j2 = 0; j2 < 4; j2++) {
                const uint32_t a = (uint32_t)(((j2 * 16 + krow) * APITCH + k * 16 + kcol) * 2);
                ldsm4(bh[j2], uKh + a);
                ldsm4(bl[j2], uKl + a);
            }
#pragma unroll
            for (int j2 = 0; j2 < 4; j2++) {
                mma16816(s[2*j2],   qh[k], &bh[j2][0]);
                mma16816(s[2*j2],   qh[k], &bl[j2][0]);
                mma16816(s[2*j2],   ql[k], &bh[j2][0]);
                mma16816(s[2*j2+1], qh[k], &bh[j2][2]);
                mma16816(s[2*j2+1], qh[k], &bl[j2][2]);
                mma16816(s[2*j2+1], ql[k], &bh[j2][2]);
            }
        }

        if (t == qt) {  // diagonal tile: block-causal mask (8-granularity)
            const int rb0 = warp * 2;       // row block of rows 0-7 slice
#pragma unroll
            for (int j = 0; j < 8; j++) {
                if (j > rb0)     { s[j][0] = -1e30f; s[j][1] = -1e30f; }
                if (j > rb0 + 1) { s[j][2] = -1e30f; s[j][3] = -1e30f; }
            }
        }

        // online softmax
        float mx0 = -1e30f, mx1 = -1e30f;
#pragma unroll
        for (int j = 0; j < 8; j++) {
            mx0 = fmaxf(mx0, fmaxf(s[j][0], s[j][1]));
            mx1 = fmaxf(mx1, fmaxf(s[j][2], s[j][3]));
        }
        mx0 = fmaxf(mx0, __shfl_xor_sync(0xffffffffu, mx0, 1));
        mx0 = fmaxf(mx0, __shfl_xor_sync(0xffffffffu, mx0, 2));
        mx1 = fmaxf(mx1, __shfl_xor_sync(0xffffffffu, mx1, 1));
        mx1 = fmaxf(mx1, __shfl_xor_sync(0xffffffffu, mx1, 2));
        const float mn0 = fmaxf(m0, mx0);
        const float mn1 = fmaxf(m1, mx1);
        const float cr0 = __expf(m0 - mn0);
        const float cr1 = __expf(m1 - mn1);
        float ps0 = 0.f, ps1 = 0.f;
#pragma unroll
        for (int j = 0; j < 8; j++) {
            s[j][0] = __expf(s[j][0] - mn0);
            s[j][1] = __expf(s[j][1] - mn0);
            s[j][2] = __expf(s[j][2] - mn1);
            s[j][3] = __expf(s[j][3] - mn1);
            ps0 += s[j][0] + s[j][1];
            ps1 += s[j][2] + s[j][3];
        }
        ps0 += __shfl_xor_sync(0xffffffffu, ps0, 1);
        ps0 += __shfl_xor_sync(0xffffffffu, ps0, 2);
        ps1 += __shfl_xor_sync(0xffffffffu, ps1, 1);
        ps1 += __shfl_xor_sync(0xffffffffu, ps1, 2);
        l0 = l0 * cr0 + ps0;  m0 = mn0;
        l1 = l1 * cr1 + ps1;  m1 = mn1;
#pragma unroll
        for (int j = 0; j < 8; j++) {
            o[j][0] *= cr0; o[j][1] *= cr0;
            o[j][2] *= cr1; o[j][3] *= cr1;
        }

        // P fragments (bf16 hi/lo) directly from S C-frags
        uint32_t pH[4][4], pL[4][4];
#pragma unroll
        for (int tt = 0; tt < 4; tt++) {
            split_pack2(s[2*tt][0],   s[2*tt][1],   pH[tt][0], pL[tt][0]);
            split_pack2(s[2*tt][2],   s[2*tt][3],   pH[tt][1], pL[tt][1]);
            split_pack2(s[2*tt+1][0], s[2*tt+1][1], pH[tt][2], pL[tt][2]);
            split_pack2(s[2*tt+1][2], s[2*tt+1][3], pH[tt][3], pL[tt][3]);
        }

        // O += P @ V  (3-product split)
#pragma unroll
        for (int tt = 0; tt < 4; tt++) {
#pragma unroll
            for (int j2 = 0; j2 < 4; j2++) {
                uint32_t vh4[4], vl4[4];
                const uint32_t a = (uint32_t)(((tt * 16 + vrow) * APITCH + j2 * 16 + vcol) * 2);
                ldsm4t(vh4, uVh + a);
                ldsm4t(vl4, uVl + a);
                mma16816(o[2*j2],   pH[tt], &vh4[0]);
                mma16816(o[2*j2],   pH[tt], &vl4[0]);
                mma16816(o[2*j2],   pL[tt], &vh4[0]);
                mma16816(o[2*j2+1], pH[tt], &vh4[2]);
                mma16816(o[2*j2+1], pH[tt], &vl4[2]);
                mma16816(o[2*j2+1], pL[tt], &vh4[2]);
            }
        }
    }

    // epilogue: normalize, split, write
    const float inv0 = 1.f / l0;
    const float inv1 = 1.f / l1;
    const size_t row0 = (size_t)(b * SEQ + q0 + warp * 16 + (lane >> 2));
    const size_t row1 = row0 + 8;
#pragma unroll
    for (int j = 0; j < 8; j++) {
        const int col = h * HD + j * 8 + (lane & 3) * 2;
        __nv_bfloat16 hh, ll;
        split2(o[j][0] * inv0, hh, ll); Ohi[row0 * DIM + col]     = hh; Olo[row0 * DIM + col]     = ll;
        split2(o[j][1] * inv0, hh, ll); Ohi[row0 * DIM + col + 1] = hh; Olo[row0 * DIM + col + 1] = ll;
        split2(o[j][2] * inv1, hh, ll); Ohi[row1 * DIM + col]     = hh; Olo[row1 * DIM + col]     = ll;
        split2(o[j][3] * inv1, hh, ll); Ohi[row1 * DIM + col + 1] = hh; Olo[row1 * DIM + col + 1] = ll;
    }
}

// ---------------- launch ----------------
extern "C" void kernel_launch(void* const* d_in, const int* in_sizes, int n_in,
                              void* d_out, int out_size)
{
    const float* x   = (const float*)d_in[0];
    const float* vec = (const float*)d_in[1];
    const float* wq  = (const float*)d_in[2];
    const float* wk  = (const float*)d_in[3];
    const float* wv  = (const float*)d_in[4];
    const float* wo  = (const float*)d_in[5];
    const float* w1  = (const float*)d_in[6];
    const float* w2  = (const float*)d_in[7];
    const float* w3  = (const float*)d_in[8];
    const float* maw = (const float*)d_in[9];
    const float* mab = (const float*)d_in[10];
    const float* mfw = (const float*)d_in[11];
    const float* mfb = (const float*)d_in[12];
    const float* n1w = (const float*)d_in[13];
    const float* n2w = (const float*)d_in[14];
    const float* fc  = (const float*)d_in[15];
    const float* fs  = (const float*)d_in[16];
    float* out = (float*)d_out;

    __nv_bfloat16 *Whi, *Wlo, *SVhi, *SVlo, *XNhi, *XNlo, *AOhi, *AOlo, *HNhi, *HNlo, *G1hi, *G1lo;
    float *MODA, *MODF, *Qb, *Kb, *Vb, *H, *F1, *F3;
    cudaGetSymbolAddress((void**)&Whi,  g_Whi);
    cudaGetSymbolAddress((void**)&Wlo,  g_Wlo);
    cudaGetSymbolAddress((void**)&SVhi, g_SVhi);
    cudaGetSymbolAddress((void**)&SVlo, g_SVlo);
    cudaGetSymbolAddress((void**)&XNhi, g_XNhi);
    cudaGetSymbolAddress((void**)&XNlo, g_XNlo);
    cudaGetSymbolAddress((void**)&AOhi, g_AOhi);
    cudaGetSymbolAddress((void**)&AOlo, g_AOlo);
    cudaGetSymbolAddress((void**)&HNhi, g_HNhi);
    cudaGetSymbolAddress((void**)&HNlo, g_HNlo);
    cudaGetSymbolAddress((void**)&G1hi, g_G1hi);
    cudaGetSymbolAddress((void**)&G1lo, g_G1lo);
    cudaGetSymbolAddress((void**)&MODA, g_MODA);
    cudaGetSymbolAddress((void**)&MODF, g_MODF);
    cudaGetSymbolAddress((void**)&Qb,   g_Q);
    cudaGetSymbolAddress((void**)&Kb,   g_Kc);
    cudaGetSymbolAddress((void**)&Vb,   g_Vc);
    cudaGetSymbolAddress((void**)&H,    g_H);
    cudaGetSymbolAddress((void**)&F1,   g_F1);
    cudaGetSymbolAddress((void**)&F3,   g_F3);

    const int attn_smem = 27648 * 2;   // 55296 B
    cudaFuncSetAttribute(attn_tc_kernel, cudaFuncAttributeMaxDynamicSharedMemorySize, attn_smem);

    // 0) split all weights (one launch)
    WSegs ws;
    ws.src[0]=wq; ws.src[1]=wk; ws.src[2]=wv; ws.src[3]=wo; ws.src[4]=w1;
    ws.src[5]=w2; ws.src[6]=w3; ws.src[7]=maw; ws.src[8]=mfw;
    ws.off[0]=OFF_WQ;  ws.off[1]=OFF_WK;  ws.off[2]=OFF_WV;  ws.off[3]=OFF_WO;
    ws.off[4]=OFF_W1;  ws.off[5]=OFF_W2;  ws.off[6]=OFF_W3;  ws.off[7]=OFF_MAW;
    ws.off[8]=OFF_MFW; ws.off[9]=WTOTAL;
    wsplit_all_kernel<<<WTOTAL/1024, 256>>>(ws, Whi, Wlo);

    // 1) modulation
    silu_split_kernel<<<(MODROWS*DIM + 255)/256, 256>>>(vec, SVhi, SVlo, MODROWS*DIM);
    hgemm_kernel<1><<<dim3(24, 4), 256>>>(SVhi, SVlo, Whi+OFF_MAW, Wlo+OFF_MAW, MODA,
                                          MODROWS, 3*DIM, DIM, mab, nullptr, nullptr);
    hgemm_kernel<1><<<dim3(24, 4), 256>>>(SVhi, SVlo, Whi+OFF_MFW, Wlo+OFF_MFW, MODF,
                                          MODROWS, 3*DIM, DIM, mfb, nullptr, nullptr);

    // 2) xn
    rmsnorm_mod_split_kernel<<<MROWS, 256>>>(x, n1w, MODA, XNhi, XNlo);

    // 3) QKV projections
    hgemm_kernel<0><<<dim3(8, 32), 256>>>(XNhi, XNlo, Whi+OFF_WQ, Wlo+OFF_WQ, Qb,
                                          MROWS, DIM, DIM, nullptr, nullptr, nullptr);
    hgemm_kernel<0><<<dim3(2, 32), 256>>>(XNhi, XNlo, Whi+OFF_WK, Wlo+OFF_WK, Kb,
                                          MROWS, NKV*HD, DIM, nullptr, nullptr, nullptr);
    hgemm_kernel<0><<<dim3(2, 32), 256>>>(XNhi, XNlo, Whi+OFF_WV, Wlo+OFF_WV, Vb,
                                          MROWS, NKV*HD, DIM, nullptr, nullptr, nullptr);

    // 4) rope
    rope_kernel<<<(MROWS*(DIM/2)    + 255)/256, 256>>>(Qb, fc, fs, DIM);
    rope_kernel<<<(MROWS*(NKV*HD/2) + 255)/256, 256>>>(Kb, fc, fs, NKV*HD);

    // 5) attention (tensor core)
    attn_tc_kernel<<<dim3(16, 16, 4), 128, attn_smem>>>(Qb, Kb, Vb, AOhi, AOlo);

    // 6) h = x + gate_a * (AO @ wo^T)
    hgemm_kernel<2><<<dim3(8, 32), 256>>>(AOhi, AOlo, Whi+OFF_WO, Wlo+OFF_WO, H,
                                          MROWS, DIM, DIM, nullptr, x, MODA);

    // 7) hn
    rmsnorm_mod_split_kernel<<<MROWS, 256>>>(H, n2w, MODF, HNhi, HNlo);

    // 8) FFN
    hgemm_kernel<0><<<dim3(8, 32), 256>>>(HNhi, HNlo, Whi+OFF_W1, Wlo+OFF_W1, F1,
                                          MROWS, DIM, DIM, nullptr, nullptr, nullptr);
    hgemm_kernel<0><<<dim3(8, 32), 256>>>(HNhi, HNlo, Whi+OFF_W3, Wlo+OFF_W3, F3,
                                          MROWS, DIM, DIM, nullptr, nullptr, nullptr);
    swiglu_split_kernel<<<(MROWS*DIM + 255)/256, 256>>>(F1, F3, G1hi, G1lo, MROWS*DIM);
    hgemm_kernel<2><<<dim3(8, 32), 256>>>(G1hi, G1lo, Whi+OFF_W2, Wlo+OFF_W2, out,
                                          MROWS, DIM, DIM, nullptr, H, MODF);
}

// round 7
// speedup vs baseline: 3.1541x; 1.1018x over previous
#include <cuda_runtime.h>
#include <cuda_bf16.h>
#include <math.h>
#include <stdint.h>

// ---------------- problem constants ----------------
#define BATCH   4
#define SEQ     1024
#define DIM     1024
#define NH      16
#define NKV     4
#define HD      64
#define MROWS   (BATCH*SEQ)     // 4096
#define MODROWS (BATCH*128)     // 512

// weight split offsets (elements) — wq,wk,wv adjacent; w1,w3 adjacent; maw,mfw adjacent
#define OFF_WQ  0
#define OFF_WK  1048576
#define OFF_WV  1310720
#define OFF_WO  1572864
#define OFF_W1  2621440
#define OFF_W3  3670016
#define OFF_W2  4718592
#define OFF_MAW 5767168
#define OFF_MFW 8912896
#define WTOTAL  12058624

// ---------------- device scratch ----------------
__device__ __nv_bfloat16 g_Whi[WTOTAL];
__device__ __nv_bfloat16 g_Wlo[WTOTAL];

__device__ __nv_bfloat16 g_SVhi[MODROWS*DIM];
__device__ __nv_bfloat16 g_SVlo[MODROWS*DIM];
__device__ __nv_bfloat16 g_XNhi[MROWS*DIM];
__device__ __nv_bfloat16 g_XNlo[MROWS*DIM];
__device__ __nv_bfloat16 g_AOhi[MROWS*DIM];
__device__ __nv_bfloat16 g_AOlo[MROWS*DIM];
__device__ __nv_bfloat16 g_HNhi[MROWS*DIM];
__device__ __nv_bfloat16 g_HNlo[MROWS*DIM];
__device__ __nv_bfloat16 g_G1hi[MROWS*DIM];
__device__ __nv_bfloat16 g_G1lo[MROWS*DIM];

__device__ __nv_bfloat16 g_Qhi[MROWS*DIM];
__device__ __nv_bfloat16 g_Qlo[MROWS*DIM];
__device__ __nv_bfloat16 g_Khi[MROWS*NKV*HD];
__device__ __nv_bfloat16 g_Klo[MROWS*NKV*HD];
__device__ __nv_bfloat16 g_Vhi[MROWS*NKV*HD];
__device__ __nv_bfloat16 g_Vlo[MROWS*NKV*HD];

__device__ float g_MOD [MODROWS*6144];
__device__ float g_QKV [MROWS*1536];
__device__ float g_FF  [MROWS*2048];
__device__ float g_H   [MROWS*DIM];

// ---------------- helpers ----------------
__device__ __forceinline__ float siluf(float x) { return x / (1.f + __expf(-x)); }

__device__ __forceinline__ void split2(float x, __nv_bfloat16& h, __nv_bfloat16& l) {
    h = __float2bfloat16(x);
    l = __float2bfloat16(x - __bfloat162float(h));
}

__device__ __forceinline__ void split_pack2(float x0, float x1, uint32_t& hi, uint32_t& lo) {
    __nv_bfloat16 h0 = __float2bfloat16(x0);
    __nv_bfloat16 h1 = __float2bfloat16(x1);
    __nv_bfloat16 l0 = __float2bfloat16(x0 - __bfloat162float(h0));
    __nv_bfloat16 l1 = __float2bfloat16(x1 - __bfloat162float(h1));
    hi = ((uint32_t)__bfloat16_as_ushort(h1) << 16) | __bfloat16_as_ushort(h0);
    lo = ((uint32_t)__bfloat16_as_ushort(l1) << 16) | __bfloat16_as_ushort(l0);
}

__device__ __forceinline__ void ldsm4(uint32_t* r, uint32_t addr) {
    asm volatile("ldmatrix.sync.aligned.m8n8.x4.shared.b16 {%0,%1,%2,%3}, [%4];"
                 : "=r"(r[0]), "=r"(r[1]), "=r"(r[2]), "=r"(r[3]) : "r"(addr));
}

__device__ __forceinline__ void ldsm4t(uint32_t* r, uint32_t addr) {
    asm volatile("ldmatrix.sync.aligned.m8n8.x4.trans.shared.b16 {%0,%1,%2,%3}, [%4];"
                 : "=r"(r[0]), "=r"(r[1]), "=r"(r[2]), "=r"(r[3]) : "r"(addr));
}

__device__ __forceinline__ void mma16816(float* c, const uint32_t* a, const uint32_t* b) {
    asm volatile(
        "mma.sync.aligned.m16n8k16.row.col.f32.bf16.bf16.f32 "
        "{%0,%1,%2,%3}, {%4,%5,%6,%7}, {%8,%9}, {%0,%1,%2,%3};\n"
        : "+f"(c[0]), "+f"(c[1]), "+f"(c[2]), "+f"(c[3])
        : "r"(a[0]), "r"(a[1]), "r"(a[2]), "r"(a[3]), "r"(b[0]), "r"(b[1]));
}

// ---------------- split-bf16 tensor-core GEMM (R3-proven mainloop) ----------------
// EPI 0: C = acc
// EPI 1: C = acc + bias[n] (n<3072) / bias2[n-3072]
// EPI 2: C = res + gate*acc, gate = mod[(b*128+s/8)*6144 + 2048 + n]
#define SPITCH 40   // bf16 elements per smem row (80 bytes)
template<int EPI>
__global__ __launch_bounds__(256) void hgemm_kernel(
    const __nv_bfloat16* __restrict__ Ahi, const __nv_bfloat16* __restrict__ Alo,
    const __nv_bfloat16* __restrict__ Whi, const __nv_bfloat16* __restrict__ Wlo,
    float* __restrict__ C, int M, int N, int K,
    const float* __restrict__ bias, const float* __restrict__ bias2,
    const float* __restrict__ res,
    const float* __restrict__ mod)
{
    __shared__ __align__(16) __nv_bfloat16 sAh[128*SPITCH];
    __shared__ __align__(16) __nv_bfloat16 sAl[128*SPITCH];
    __shared__ __align__(16) __nv_bfloat16 sBh[128*SPITCH];
    __shared__ __align__(16) __nv_bfloat16 sBl[128*SPITCH];

    const int bm = blockIdx.y * 128;
    const int bn = blockIdx.x * 128;
    const int tid = threadIdx.x;
    const int lane = tid & 31;
    const int warp = tid >> 5;
    const int m0 = (warp >> 2) * 64;
    const int n0 = (warp & 3) * 32;
    const int group = lane >> 2, tig = lane & 3;

    const int gr = tid >> 2;
    const int gk = (tid & 3) * 8;
    const size_t a0off = (size_t)(bm + gr) * K + gk;
    const size_t a1off = (size_t)(bm + 64 + gr) * K + gk;
    const size_t b0off = (size_t)(bn + gr) * K + gk;
    const size_t b1off = (size_t)(bn + 64 + gr) * K + gk;

    const int s0 = gr * SPITCH + gk;
    const int s1 = (64 + gr) * SPITCH + gk;

    const uint32_t uAh = (uint32_t)__cvta_generic_to_shared(sAh);
    const uint32_t uAl = (uint32_t)__cvta_generic_to_shared(sAl);
    const uint32_t uBh = (uint32_t)__cvta_generic_to_shared(sBh);
    const uint32_t uBl = (uint32_t)__cvta_generic_to_shared(sBl);
    const uint32_t aoffL = (uint32_t)((m0 + (lane & 7) + ((lane >> 3) & 1) * 8) * 80 + ((lane >> 4) & 1) * 16);
    const uint32_t boffL = (uint32_t)((n0 + (lane & 7) + ((lane >> 4) & 1) * 8) * 80 + ((lane >> 3) & 1) * 16);

    float c[4][4][4];
#pragma unroll
    for (int i = 0; i < 4; i++)
#pragma unroll
        for (int j = 0; j < 4; j++)
#pragma unroll
            for (int q = 0; q < 4; q++) c[i][j][q] = 0.f;

    uint4 rAh0 = *(const uint4*)(Ahi + a0off);
    uint4 rAh1 = *(const uint4*)(Ahi + a1off);
    uint4 rAl0 = *(const uint4*)(Alo + a0off);
    uint4 rAl1 = *(const uint4*)(Alo + a1off);
    uint4 rBh0 = *(const uint4*)(Whi + b0off);
    uint4 rBh1 = *(const uint4*)(Whi + b1off);
    uint4 rBl0 = *(const uint4*)(Wlo + b0off);
    uint4 rBl1 = *(const uint4*)(Wlo + b1off);

    for (int k0 = 0; k0 < K; k0 += 32) {
        __syncthreads();
        *(uint4*)&sAh[s0] = rAh0;  *(uint4*)&sAh[s1] = rAh1;
        *(uint4*)&sAl[s0] = rAl0;  *(uint4*)&sAl[s1] = rAl1;
        *(uint4*)&sBh[s0] = rBh0;  *(uint4*)&sBh[s1] = rBh1;
        *(uint4*)&sBl[s0] = rBl0;  *(uint4*)&sBl[s1] = rBl1;
        __syncthreads();

        if (k0 + 32 < K) {
            const int kn = k0 + 32;
            rAh0 = *(const uint4*)(Ahi + a0off + kn);
            rAh1 = *(const uint4*)(Ahi + a1off + kn);
            rAl0 = *(const uint4*)(Alo + a0off + kn);
            rAl1 = *(const uint4*)(Alo + a1off + kn);
            rBh0 = *(const uint4*)(Whi + b0off + kn);
            rBh1 = *(const uint4*)(Whi + b1off + kn);
            rBl0 = *(const uint4*)(Wlo + b0off + kn);
            rBl1 = *(const uint4*)(Wlo + b1off + kn);
        }

#pragma unroll
        for (int ks = 0; ks < 2; ks++) {
            uint32_t Ah[4][4], Al[4][4], Bh[4][2], Bl[4][2];
            const uint32_t ao = aoffL + ks * 32;
            const uint32_t bo = boffL + ks * 32;
#pragma unroll
            for (int mf = 0; mf < 4; mf++) {
                ldsm4(Ah[mf], uAh + ao + mf * (16 * 80));
                ldsm4(Al[mf], uAl + ao + mf * (16 * 80));
            }
#pragma unroll
            for (int p = 0; p < 2; p++) {
                uint32_t t[4];
                ldsm4(t, uBh + bo + p * (16 * 80));
                Bh[2*p][0] = t[0]; Bh[2*p][1] = t[1];
                Bh[2*p+1][0] = t[2]; Bh[2*p+1][1] = t[3];
                ldsm4(t, uBl + bo + p * (16 * 80));
                Bl[2*p][0] = t[0]; Bl[2*p][1] = t[1];
                Bl[2*p+1][0] = t[2]; Bl[2*p+1][1] = t[3];
            }
#pragma unroll
            for (int mf = 0; mf < 4; mf++) {
#pragma unroll
                for (int nf = 0; nf < 4; nf++) {
                    mma16816(c[mf][nf], Ah[mf], Bh[nf]);
                    mma16816(c[mf][nf], Ah[mf], Bl[nf]);
                    mma16816(c[mf][nf], Al[mf], Bh[nf]);
                }
            }
        }
    }

#pragma unroll
    for (int mf = 0; mf < 4; mf++) {
#pragma unroll
        for (int nf = 0; nf < 4; nf++) {
            const int mA = bm + m0 + mf * 16 + group;
            const int nA = bn + n0 + nf * 8 + tig * 2;
            float* p0 = C + (size_t)mA * N + nA;
            float* p1 = C + (size_t)(mA + 8) * N + nA;
            float v0 = c[mf][nf][0], v1 = c[mf][nf][1];
            float v2 = c[mf][nf][2], v3 = c[mf][nf][3];
            if (EPI == 1) {
                const float* bb = (bn < 3072) ? bias : bias2;
                const int nB = nA - ((bn < 3072) ? 0 : 3072);
                const float b0v = bb[nB], b1v = bb[nB + 1];
                v0 += b0v; v1 += b1v; v2 += b0v; v3 += b1v;
            } else if (EPI == 2) {
                const int ba = mA >> 10, sa = mA & 1023;
                const float* g0 = mod + (size_t)((ba << 7) + (sa >> 3)) * 6144 + 2048;
                const int bb2 = (mA + 8) >> 10, sb = (mA + 8) & 1023;
                const float* g1 = mod + (size_t)((bb2 << 7) + (sb >> 3)) * 6144 + 2048;
                v0 = res[(size_t)mA * N + nA]       + g0[nA]     * v0;
                v1 = res[(size_t)mA * N + nA + 1]   + g0[nA + 1] * v1;
                v2 = res[(size_t)(mA+8) * N + nA]   + g1[nA]     * v2;
                v3 = res[(size_t)(mA+8) * N + nA+1] + g1[nA + 1] * v3;
            }
            *(float2*)p0 = make_float2(v0, v1);
            *(float2*)p1 = make_float2(v2, v3);
        }
    }
}

// ---------------- merged weight split ----------------
struct WSegs {
    const float* src[9];
    int off[10];
};

__global__ __launch_bounds__(256) void wsplit_all_kernel(
    WSegs ws, __nv_bfloat16* __restrict__ hi, __nv_bfloat16* __restrict__ lo)
{
    const int base = blockIdx.x * 1024 + threadIdx.x * 4;
    int seg = 0;
#pragma unroll
    for (int k = 1; k < 9; k++) if (base >= ws.off[k]) seg = k;
    const float* src = ws.src[seg] + (base - ws.off[seg]);
    float4 v = *(const float4*)src;
    uint32_t h01, l01, h23, l23;
    split_pack2(v.x, v.y, h01, l01);
    split_pack2(v.z, v.w, h23, l23);
    *(uint2*)(hi + base) = make_uint2(h01, h23);
    *(uint2*)(lo + base) = make_uint2(l01, l23);
}

// ---------------- pointwise kernels ----------------
__global__ void silu_split_kernel(const float* __restrict__ in,
                                  __nv_bfloat16* __restrict__ hi,
                                  __nv_bfloat16* __restrict__ lo, int n)
{
    int i = blockIdx.x * blockDim.x + threadIdx.x;
    if (i >= n) return;
    __nv_bfloat16 h, l;
    split2(siluf(in[i]), h, l);
    hi[i] = h; lo[i] = l;
}

// FF[m, 0:1024]=f1, FF[m, 1024:2048]=f3 -> G1 = silu(f1)*f3 split
__global__ void swiglu_split_kernel(const float* __restrict__ FF,
                                    __nv_bfloat16* __restrict__ hi,
                                    __nv_bfloat16* __restrict__ lo)
{
    int i = blockIdx.x * blockDim.x + threadIdx.x;
    const int m = i >> 10, n = i & 1023;
    const float a  = FF[((size_t)m << 11) + n];
    const float b3 = FF[((size_t)m << 11) + 1024 + n];
    __nv_bfloat16 h, l;
    split2(siluf(a) * b3, h, l);
    hi[i] = h; lo[i] = l;
}

__global__ __launch_bounds__(256) void rmsnorm_mod_split_kernel(
    const float* __restrict__ X, const float* __restrict__ w,
    const float* __restrict__ mod, int seg,
    __nv_bfloat16* __restrict__ hi, __nv_bfloat16* __restrict__ lo)
{
    const int m = blockIdx.x;
    const float* x = X + (size_t)m * DIM;
    const int b = m >> 10;
    const int s = m & 1023;
    const float* md = mod + (size_t)((b << 7) + (s >> 3)) * 6144 + seg;
    const int tid = threadIdx.x;

    float v[4];
    float ss = 0.f;
#pragma unroll
    for (int i = 0; i < 4; i++) { v[i] = x[tid + 256 * i]; ss += v[i] * v[i]; }
#pragma unroll
    for (int off = 16; off; off >>= 1) ss += __shfl_xor_sync(0xffffffffu, ss, off);
    __shared__ float wsum[8];
    if ((tid & 31) == 0) wsum[tid >> 5] = ss;
    __syncthreads();
    float total = wsum[0] + wsum[1] + wsum[2] + wsum[3]
                + wsum[4] + wsum[5] + wsum[6] + wsum[7];
    const float inv = rsqrtf(total * (1.f / 1024.f) + 1e-6f);
#pragma unroll
    for (int i = 0; i < 4; i++) {
        const int n = tid + 256 * i;
        float y = v[i] * inv * w[n] * (1.f + md[1024 + n]) + md[n];
        __nv_bfloat16 h, l;
        split2(y, h, l);
        hi[(size_t)m * DIM + n] = h;
        lo[(size_t)m * DIM + n] = l;
    }
}

// rope + scale + split for Q. QKV fp32 rows of 1536, Q = cols [0,1024).
__global__ void rope_split_q_kernel(const float* __restrict__ QKV,
                                    const float* __restrict__ fc, const float* __restrict__ fs,
                                    __nv_bfloat16* __restrict__ Qhi, __nv_bfloat16* __restrict__ Qlo)
{
    const int idx = blockIdx.x * blockDim.x + threadIdx.x;   // 4096*512
    const int m = idx >> 9;
    const int p = idx & 511;         // h*32 + i
    const int i = p & 31;
    const int s = m & 1023;
    const float cc = fc[s * 32 + i];
    const float sn = fs[s * 32 + i];
    const float* src = QKV + (size_t)m * 1536 + (p << 1);
    const float x1 = src[0], x2 = src[1];
    const float y1 = (x1 * cc - x2 * sn) * 0.125f;
    const float y2 = (x1 * sn + x2 * cc) * 0.125f;
    uint32_t h, l;
    split_pack2(y1, y2, h, l);
    ((uint32_t*)Qhi)[m * 512 + p] = h;
    ((uint32_t*)Qlo)[m * 512 + p] = l;
}

// rope+split K (cols [1024,1280)), split V (cols [1280,1536)).
__global__ void rope_split_kv_kernel(const float* __restrict__ QKV,
                                     const float* __restrict__ fc, const float* __restrict__ fs,
                                     __nv_bfloat16* __restrict__ Khi, __nv_bfloat16* __restrict__ Klo,
                                     __nv_bfloat16* __restrict__ Vhi, __nv_bfloat16* __restrict__ Vlo)
{
    const int idx = blockIdx.x * blockDim.x + threadIdx.x;   // 4096*128
    const int m = idx >> 7;
    const int p = idx & 127;         // kvh*32 + i
    const int i = p & 31;
    const int s = m & 1023;
    const float cc = fc[s * 32 + i];
    const float sn = fs[s * 32 + i];
    const float* srcK = QKV + (size_t)m * 1536 + 1024 + (p << 1);
    const float* srcV = QKV + (size_t)m * 1536 + 1280 + (p << 1);
    const float x1 = srcK[0], x2 = srcK[1];
    uint32_t h, l;
    split_pack2(x1 * cc - x2 * sn, x1 * sn + x2 * cc, h, l);
    ((uint32_t*)Khi)[m * 128 + p] = h;
    ((uint32_t*)Klo)[m * 128 + p] = l;
    split_pack2(srcV[0], srcV[1], h, l);
    ((uint32_t*)Vhi)[m * 128 + p] = h;
    ((uint32_t*)Vlo)[m * 128 + p] = l;
}

// ---------------- tensor-core split-bf16 flash attention (R3-proven structure) ----------------
// smem elements: Qh 0, Ql 4608, Kh 9216, Kl 13824, Vh 18432, Vl 23040; pitch AP=72; total 55296 B
#define AP 72
#define ATTN_SMEM 55296
__global__ __launch_bounds__(128) void attn_tc_kernel(
    const __nv_bfloat16* __restrict__ Qhi, const __nv_bfloat16* __restrict__ Qlo,
    const __nv_bfloat16* __restrict__ Khi, const __nv_bfloat16* __restrict__ Klo,
    const __nv_bfloat16* __restrict__ Vhi, const __nv_bfloat16* __restrict__ Vlo,
    __nv_bfloat16* __restrict__ Ohi, __nv_bfloat16* __restrict__ Olo)
{
    extern __shared__ __align__(16) __nv_bfloat16 sb[];
    __nv_bfloat16* Qh = sb;
    __nv_bfloat16* Ql = sb + 4608;
    __nv_bfloat16* Kh = sb + 9216;
    __nv_bfloat16* Kl = sb + 13824;
    __nv_bfloat16* Vh = sb + 18432;
    __nv_bfloat16* Vl = sb + 23040;

    const int qt = gridDim.x - 1 - blockIdx.x;   // big tiles first
    const int h = blockIdx.y, b = blockIdx.z;
    const int kvh = h >> 2;
    const int tid = threadIdx.x, warp = tid >> 5, lane = tid & 31;
    const int q0 = qt << 6;

    // load Q tile (64x64, bf16 hi/lo, pre-scaled/roped)
    for (int i = tid; i < 512; i += 128) {
        const int r = i >> 3, sg = (i & 7) * 8;
        const size_t g = (size_t)(b * SEQ + q0 + r) * DIM + h * HD + sg;
        *(uint4*)(Qh + r * AP + sg) = *(const uint4*)(Qhi + g);
        *(uint4*)(Ql + r * AP + sg) = *(const uint4*)(Qlo + g);
    }
    __syncthreads();

    // Q fragments in registers
    const uint32_t uQh = (uint32_t)__cvta_generic_to_shared(Qh);
    const uint32_t uQl = (uint32_t)__cvta_generic_to_shared(Ql);
    uint32_t qh[4][4], ql[4][4];
    {
        const int qrow = warp * 16 + (lane & 15);
#pragma unroll
        for (int k = 0; k < 4; k++) {
            const uint32_t a = (uint32_t)((qrow * AP + k * 16 + (lane >> 4) * 8) * 2);
            ldsm4(qh[k], uQh + a);
            ldsm4(ql[k], uQl + a);
        }
    }

    const uint32_t uKh = (uint32_t)__cvta_generic_to_shared(Kh);
    const uint32_t uKl = (uint32_t)__cvta_generic_to_shared(Kl);
    const uint32_t uVh = (uint32_t)__cvta_generic_to_shared(Vh);
    const uint32_t uVl = (uint32_t)__cvta_generic_to_shared(Vl);
    const int krow = (lane & 7) + ((lane >> 4) & 1) * 8;
    const int kcol = ((lane >> 3) & 1) * 8;
    const int vrow = (lane & 7) + ((lane >> 3) & 1) * 8;
    const int vcol = ((lane >> 4) & 1) * 8;

    float o[8][4];
#pragma unroll
    for (int j = 0; j < 8; j++)
#pragma unroll
        for (int q = 0; q < 4; q++) o[j][q] = 0.f;
    float m0 = -1e30f, m1 = -1e30f, l0 = 0.f, l1 = 0.f;

    for (int t = 0; t <= qt; t++) {
        __syncthreads();
        for (int i = tid; i < 512; i += 128) {
            const int r = i >> 3, sg = (i & 7) * 8;
            const size_t g = (size_t)(b * SEQ + t * 64 + r) * 256 + kvh * 64 + sg;
            *(uint4*)(Kh + r * AP + sg) = *(const uint4*)(Khi + g);
            *(uint4*)(Kl + r * AP + sg) = *(const uint4*)(Klo + g);
            *(uint4*)(Vh + r * AP + sg) = *(const uint4*)(Vhi + g);
            *(uint4*)(Vl + r * AP + sg) = *(const uint4*)(Vlo + g);
        }
        __syncthreads();

        // S = Q @ K^T  (3-product split)
        float sc[8][4];
#pragma unroll
        for (int j = 0; j < 8; j++)
#pragma unroll
            for (int q = 0; q < 4; q++) sc[j][q] = 0.f;
#pragma unroll
        for (int k = 0; k < 4; k++) {
            uint32_t bh[4][4], bl[4][4];
#pragma unroll
            for (int j2 = 0; j2 < 4; j2++) {
                const uint32_t a = (uint32_t)(((j2 * 16 + krow) * AP + k * 16 + kcol) * 2);
                ldsm4(bh[j2], uKh + a);
                ldsm4(bl[j2], uKl + a);
            }
#pragma unroll
            for (int j2 = 0; j2 < 4; j2++) {
                mma16816(sc[2*j2],   qh[k], &bh[j2][0]);
                mma16816(sc[2*j2],   qh[k], &bl[j2][0]);
                mma16816(sc[2*j2],   ql[k], &bh[j2][0]);
                mma16816(sc[2*j2+1], qh[k], &bh[j2][2]);
                mma16816(sc[2*j2+1], qh[k], &bl[j2][2]);
                mma16816(sc[2*j2+1], ql[k], &bh[j2][2]);
            }
        }

        if (t == qt) {  // diagonal tile: block-causal mask (8-granularity)
            const int rb0 = warp * 2;
#pragma unroll
            for (int j = 0; j < 8; j++) {
                if (j > rb0)     { sc[j][0] = -1e30f; sc[j][1] = -1e30f; }
                if (j > rb0 + 1) { sc[j][2] = -1e30f; sc[j][3] = -1e30f; }
            }
        }

        // online softmax
        float mx0 = -1e30f, mx1 = -1e30f;
#pragma unroll
        for (int j = 0; j < 8; j++) {
            mx0 = fmaxf(mx0, fmaxf(sc[j][0], sc[j][1]));
            mx1 = fmaxf(mx1, fmaxf(sc[j][2], sc[j][3]));
        }
        mx0 = fmaxf(mx0, __shfl_xor_sync(0xffffffffu, mx0, 1));
        mx0 = fmaxf(mx0, __shfl_xor_sync(0xffffffffu, mx0, 2));
        mx1 = fmaxf(mx1, __shfl_xor_sync(0xffffffffu, mx1, 1));
        mx1 = fmaxf(mx1, __shfl_xor_sync(0xffffffffu, mx1, 2));
        const float mn0 = fmaxf(m0, mx0);
        const float mn1 = fmaxf(m1, mx1);
        const float cr0 = __expf(m0 - mn0);
        const float cr1 = __expf(m1 - mn1);
        float ps0 = 0.f, ps1 = 0.f;
#pragma unroll
        for (int j = 0; j < 8; j++) {
            sc[j][0] = __expf(sc[j][0] - mn0);
            sc[j][1] = __expf(sc[j][1] - mn0);
            sc[j][2] = __expf(sc[j][2] - mn1);
            sc[j][3] = __expf(sc[j][3] - mn1);
            ps0 += sc[j][0] + sc[j][1];
            ps1 += sc[j][2] + sc[j][3];
        }
        ps0 += __shfl_xor_sync(0xffffffffu, ps0, 1);
        ps0 += __shfl_xor_sync(0xffffffffu, ps0, 2);
        ps1 += __shfl_xor_sync(0xffffffffu, ps1, 1);
        ps1 += __shfl_xor_sync(0xffffffffu, ps1, 2);
        l0 = l0 * cr0 + ps0;  m0 = mn0;
        l1 = l1 * cr1 + ps1;  m1 = mn1;
#pragma unroll
        for (int j = 0; j < 8; j++) {
            o[j][0] *= cr0; o[j][1] *= cr0;
            o[j][2] *= cr1; o[j][3] *= cr1;
        }

        // P fragments (bf16 hi/lo) directly from S C-frags
        uint32_t pH[4][4], pL[4][4];
#pragma unroll
        for (int tt = 0; tt < 4; tt++) {
            split_pack2(sc[2*tt][0],   sc[2*tt][1],   pH[tt][0], pL[tt][0]);
            split_pack2(sc[2*tt][2],   sc[2*tt][3],   pH[tt][1], pL[tt][1]);
            split_pack2(sc[2*tt+1][0], sc[2*tt+1][1], pH[tt][2], pL[tt][2]);
            split_pack2(sc[2*tt+1][2], sc[2*tt+1][3], pH[tt][3], pL[tt][3]);
        }

        // O += P @ V  (3-product split)
#pragma unroll
        for (int tt = 0; tt < 4; tt++) {
#pragma unroll
            for (int j2 = 0; j2 < 4; j2++) {
                uint32_t vh4[4], vl4[4];
                const uint32_t a = (uint32_t)(((tt * 16 + vrow) * AP + j2 * 16 + vcol) * 2);
                ldsm4t(vh4, uVh + a);
                ldsm4t(vl4, uVl + a);
                mma16816(o[2*j2],   pH[tt], &vh4[0]);
                mma16816(o[2*j2],   pH[tt], &vl4[0]);
                mma16816(o[2*j2],   pL[tt], &vh4[0]);
                mma16816(o[2*j2+1], pH[tt], &vh4[2]);
                mma16816(o[2*j2+1], pH[tt], &vl4[2]);
                mma16816(o[2*j2+1], pL[tt], &vh4[2]);
            }
        }
    }

    const float inv0 = 1.f / l0;
    const float inv1 = 1.f / l1;
    const size_t row0 = (size_t)(b * SEQ + q0 + warp * 16 + (lane >> 2));
    const size_t row1 = row0 + 8;
#pragma unroll
    for (int j = 0; j < 8; j++) {
        const int col = h * HD + j * 8 + (lane & 3) * 2;
        __nv_bfloat16 hh, ll;
        split2(o[j][0] * inv0, hh, ll); Ohi[row0 * DIM + col]     = hh; Olo[row0 * DIM + col]     = ll;
        split2(o[j][1] * inv0, hh, ll); Ohi[row0 * DIM + col + 1] = hh; Olo[row0 * DIM + col + 1] = ll;
        split2(o[j][2] * inv1, hh, ll); Ohi[row1 * DIM + col]     = hh; Olo[row1 * DIM + col]     = ll;
        split2(o[j][3] * inv1, hh, ll); Ohi[row1 * DIM + col + 1] = hh; Olo[row1 * DIM + col + 1] = ll;
    }
}

// ---------------- launch ----------------
extern "C" void kernel_launch(void* const* d_in, const int* in_sizes, int n_in,
                              void* d_out, int out_size)
{
    const float* x   = (const float*)d_in[0];
    const float* vec = (const float*)d_in[1];
    const float* wq  = (const float*)d_in[2];
    const float* wk  = (const float*)d_in[3];
    const float* wv  = (const float*)d_in[4];
    const float* wo  = (const float*)d_in[5];
    const float* w1  = (const float*)d_in[6];
    const float* w2  = (const float*)d_in[7];
    const float* w3  = (const float*)d_in[8];
    const float* maw = (const float*)d_in[9];
    const float* mab = (const float*)d_in[10];
    const float* mfw = (const float*)d_in[11];
    const float* mfb = (const float*)d_in[12];
    const float* n1w = (const float*)d_in[13];
    const float* n2w = (const float*)d_in[14];
    const float* fc  = (const float*)d_in[15];
    const float* fs  = (const float*)d_in[16];
    float* out = (float*)d_out;

    __nv_bfloat16 *Whi, *Wlo, *SVhi, *SVlo, *XNhi, *XNlo, *AOhi, *AOlo, *HNhi, *HNlo, *G1hi, *G1lo;
    __nv_bfloat16 *Qhi, *Qlo, *Khi, *Klo, *Vhi, *Vlo;
    float *MOD, *QKV, *FF, *H;
    cudaGetSymbolAddress((void**)&Whi,  g_Whi);
    cudaGetSymbolAddress((void**)&Wlo,  g_Wlo);
    cudaGetSymbolAddress((void**)&SVhi, g_SVhi);
    cudaGetSymbolAddress((void**)&SVlo, g_SVlo);
    cudaGetSymbolAddress((void**)&XNhi, g_XNhi);
    cudaGetSymbolAddress((void**)&XNlo, g_XNlo);
    cudaGetSymbolAddress((void**)&AOhi, g_AOhi);
    cudaGetSymbolAddress((void**)&AOlo, g_AOlo);
    cudaGetSymbolAddress((void**)&HNhi, g_HNhi);
    cudaGetSymbolAddress((void**)&HNlo, g_HNlo);
    cudaGetSymbolAddress((void**)&G1hi, g_G1hi);
    cudaGetSymbolAddress((void**)&G1lo, g_G1lo);
    cudaGetSymbolAddress((void**)&Qhi,  g_Qhi);
    cudaGetSymbolAddress((void**)&Qlo,  g_Qlo);
    cudaGetSymbolAddress((void**)&Khi,  g_Khi);
    cudaGetSymbolAddress((void**)&Klo,  g_Klo);
    cudaGetSymbolAddress((void**)&Vhi,  g_Vhi);
    cudaGetSymbolAddress((void**)&Vlo,  g_Vlo);
    cudaGetSymbolAddress((void**)&MOD,  g_MOD);
    cudaGetSymbolAddress((void**)&QKV,  g_QKV);
    cudaGetSymbolAddress((void**)&FF,   g_FF);
    cudaGetSymbolAddress((void**)&H,    g_H);

    cudaFuncSetAttribute(attn_tc_kernel, cudaFuncAttributeMaxDynamicSharedMemorySize, ATTN_SMEM);

    // 0) split all weights (one launch)
    WSegs ws;
    ws.src[0]=wq; ws.src[1]=wk; ws.src[2]=wv; ws.src[3]=wo; ws.src[4]=w1;
    ws.src[5]=w3; ws.src[6]=w2; ws.src[7]=maw; ws.src[8]=mfw;
    ws.off[0]=OFF_WQ;  ws.off[1]=OFF_WK;  ws.off[2]=OFF_WV;  ws.off[3]=OFF_WO;
    ws.off[4]=OFF_W1;  ws.off[5]=OFF_W3;  ws.off[6]=OFF_W2;  ws.off[7]=OFF_MAW;
    ws.off[8]=OFF_MFW; ws.off[9]=WTOTAL;
    wsplit_all_kernel<<<WTOTAL/1024, 256>>>(ws, Whi, Wlo);

    // 1) modulation: one merged GEMM, N = 6144 (attn mod | ffn mod)
    silu_split_kernel<<<(MODROWS*DIM + 255)/256, 256>>>(vec, SVhi, SVlo, MODROWS*DIM);
    hgemm_kernel<1><<<dim3(48, 4), 256>>>(SVhi, SVlo, Whi+OFF_MAW, Wlo+OFF_MAW, MOD,
                                          MODROWS, 6144, DIM, mab, mfb, nullptr, nullptr);

    // 2) xn
    rmsnorm_mod_split_kernel<<<MROWS, 256>>>(x, n1w, MOD, 0, XNhi, XNlo);

    // 3) merged QKV projection, N = 1536
    hgemm_kernel<0><<<dim3(12, 32), 256>>>(XNhi, XNlo, Whi+OFF_WQ, Wlo+OFF_WQ, QKV,
                                           MROWS, 1536, DIM, nullptr, nullptr, nullptr, nullptr);

    // 4) rope + split
    rope_split_q_kernel <<<(MROWS*512)/256, 256>>>(QKV, fc, fs, Qhi, Qlo);
    rope_split_kv_kernel<<<(MROWS*128)/256, 256>>>(QKV, fc, fs, Khi, Klo, Vhi, Vlo);

    // 5) attention
    attn_tc_kernel<<<dim3(16, 16, 4), 128, ATTN_SMEM>>>(Qhi, Qlo, Khi, Klo, Vhi, Vlo, AOhi, AOlo);

    // 6) h = x + gate_a * (AO @ wo^T)
    hgemm_kernel<2><<<dim3(8, 32), 256>>>(AOhi, AOlo, Whi+OFF_WO, Wlo+OFF_WO, H,
                                          MROWS, DIM, DIM, nullptr, nullptr, x, MOD);

    // 7) hn
    rmsnorm_mod_split_kernel<<<MROWS, 256>>>(H, n2w, MOD, 3072, HNhi, HNlo);

    // 8) FFN: merged F1|F3 (N=2048), swiglu, down-proj
    hgemm_kernel<0><<<dim3(16, 32), 256>>>(HNhi, HNlo, Whi+OFF_W1, Wlo+OFF_W1, FF,
                                           MROWS, 2048, DIM, nullptr, nullptr, nullptr, nullptr);
    swiglu_split_kernel<<<(MROWS*DIM)/256, 256>>>(FF, G1hi, G1lo);
    hgemm_kernel<2><<<dim3(8, 32), 256>>>(G1hi, G1lo, Whi+OFF_W2, Wlo+OFF_W2, out,
                                          MROWS, DIM, DIM, nullptr, nullptr, H, MOD + 3072);
}

// round 10
// speedup vs baseline: 3.3440x; 1.0602x over previous
#include <cuda_runtime.h>
#include <cuda_bf16.h>
#include <math.h>
#include <stdint.h>

// ---------------- problem constants ----------------
#define BATCH   4
#define SEQ     1024
#define DIM     1024
#define NH      16
#define NKV     4
#define HD      64
#define MROWS   (BATCH*SEQ)     // 4096
#define MODROWS (BATCH*128)     // 512

// weight split offsets (elements)
#define OFF_WQ  0
#define OFF_WK  1048576
#define OFF_WV  1310720
#define OFF_WO  1572864
#define OFF_W1  2621440
#define OFF_W3  3670016
#define OFF_W2  4718592
#define OFF_MAW 5767168
#define OFF_MFW 8912896
#define WTOTAL  12058624

// ---------------- device scratch ----------------
__device__ __nv_bfloat16 g_Whi[WTOTAL];
__device__ __nv_bfloat16 g_Wlo[WTOTAL];

__device__ __nv_bfloat16 g_SVhi[MODROWS*DIM];
__device__ __nv_bfloat16 g_SVlo[MODROWS*DIM];
__device__ __nv_bfloat16 g_XNhi[MROWS*DIM];
__device__ __nv_bfloat16 g_XNlo[MROWS*DIM];
__device__ __nv_bfloat16 g_AOhi[MROWS*DIM];
__device__ __nv_bfloat16 g_AOlo[MROWS*DIM];
__device__ __nv_bfloat16 g_HNhi[MROWS*DIM];
__device__ __nv_bfloat16 g_HNlo[MROWS*DIM];
__device__ __nv_bfloat16 g_G1hi[MROWS*DIM];
__device__ __nv_bfloat16 g_G1lo[MROWS*DIM];

__device__ __nv_bfloat16 g_Qhi[MROWS*DIM];
__device__ __nv_bfloat16 g_Qlo[MROWS*DIM];
__device__ __nv_bfloat16 g_Khi[MROWS*NKV*HD];
__device__ __nv_bfloat16 g_Klo[MROWS*NKV*HD];
__device__ __nv_bfloat16 g_Vhi[MROWS*NKV*HD];
__device__ __nv_bfloat16 g_Vlo[MROWS*NKV*HD];

__device__ float g_MOD [MODROWS*6144];
__device__ float g_QKV [MROWS*1536];
__device__ float g_FF  [MROWS*2048];
__device__ float g_H   [MROWS*DIM];

// ---------------- helpers ----------------
__device__ __forceinline__ float siluf(float x) { return x / (1.f + __expf(-x)); }

__device__ __forceinline__ void split2(float x, __nv_bfloat16& h, __nv_bfloat16& l) {
    h = __float2bfloat16(x);
    l = __float2bfloat16(x - __bfloat162float(h));
}

__device__ __forceinline__ void split_pack2(float x0, float x1, uint32_t& hi, uint32_t& lo) {
    __nv_bfloat16 h0 = __float2bfloat16(x0);
    __nv_bfloat16 h1 = __float2bfloat16(x1);
    __nv_bfloat16 l0 = __float2bfloat16(x0 - __bfloat162float(h0));
    __nv_bfloat16 l1 = __float2bfloat16(x1 - __bfloat162float(h1));
    hi = ((uint32_t)__bfloat16_as_ushort(h1) << 16) | __bfloat16_as_ushort(h0);
    lo = ((uint32_t)__bfloat16_as_ushort(l1) << 16) | __bfloat16_as_ushort(l0);
}

__device__ __forceinline__ void ldsm4(uint32_t* r, uint32_t addr) {
    asm volatile("ldmatrix.sync.aligned.m8n8.x4.shared.b16 {%0,%1,%2,%3}, [%4];"
                 : "=r"(r[0]), "=r"(r[1]), "=r"(r[2]), "=r"(r[3]) : "r"(addr));
}

__device__ __forceinline__ void ldsm4t(uint32_t* r, uint32_t addr) {
    asm volatile("ldmatrix.sync.aligned.m8n8.x4.trans.shared.b16 {%0,%1,%2,%3}, [%4];"
                 : "=r"(r[0]), "=r"(r[1]), "=r"(r[2]), "=r"(r[3]) : "r"(addr));
}

__device__ __forceinline__ void mma16816(float* c, const uint32_t* a, const uint32_t* b) {
    asm volatile(
        "mma.sync.aligned.m16n8k16.row.col.f32.bf16.bf16.f32 "
        "{%0,%1,%2,%3}, {%4,%5,%6,%7}, {%8,%9}, {%0,%1,%2,%3};\n"
        : "+f"(c[0]), "+f"(c[1]), "+f"(c[2]), "+f"(c[3])
        : "r"(a[0]), "r"(a[1]), "r"(a[2]), "r"(a[3]), "r"(b[0]), "r"(b[1]));
}

// ---------------- split-bf16 tensor-core GEMM, 2-stage single-sync mainloop ----------------
// C(M,N) = A(M,K) @ W(N,K)^T. Dynamic smem, stage s at byte offset s*40960:
//   Ah +0, Al +10240, Bh +20480, Bl +30720 (row pitch 80 B, 128 rows each).
// EPI 0: C = acc
// EPI 1: C = acc + bias[n] (n<3072) / bias2[n-3072]
// EPI 2: C = res + gate*acc, gate = mod[(b*128+s/8)*6144 + 2048 + n]
#define GEMM_SMEM 81920
template<int EPI>
__global__ __launch_bounds__(256) void hgemm_kernel(
    const __nv_bfloat16* __restrict__ Ahi, const __nv_bfloat16* __restrict__ Alo,
    const __nv_bfloat16* __restrict__ Whi, const __nv_bfloat16* __restrict__ Wlo,
    float* __restrict__ C, int M, int N, int K,
    const float* __restrict__ bias, const float* __restrict__ bias2,
    const float* __restrict__ res,
    const float* __restrict__ mod)
{
    extern __shared__ __align__(16) __nv_bfloat16 gsm[];
    const uint32_t u_sm = (uint32_t)__cvta_generic_to_shared(gsm);

    const int bm = blockIdx.y * 128;
    const int bn = blockIdx.x * 128;
    const int tid = threadIdx.x;
    const int lane = tid & 31;
    const int warp = tid >> 5;
    const int m0 = (warp >> 2) * 64;
    const int n0 = (warp & 3) * 32;
    const int group = lane >> 2, tig = lane & 3;

    const int gr = tid >> 2;
    const int gk = (tid & 3) * 8;
    const size_t a0off = (size_t)(bm + gr) * K + gk;
    const size_t a1off = (size_t)(bm + 64 + gr) * K + gk;
    const size_t b0off = (size_t)(bn + gr) * K + gk;
    const size_t b1off = (size_t)(bn + 64 + gr) * K + gk;

    // smem store offsets within a stage (elements)
    const int s0 = gr * 40 + gk;
    const int s1 = (64 + gr) * 40 + gk;

    const uint32_t aoffL = (uint32_t)((m0 + (lane & 7) + ((lane >> 3) & 1) * 8) * 80 + ((lane >> 4) & 1) * 16);
    const uint32_t boffL = (uint32_t)((n0 + (lane & 7) + ((lane >> 4) & 1) * 8) * 80 + ((lane >> 3) & 1) * 16);

    float c[4][4][4];
#pragma unroll
    for (int i = 0; i < 4; i++)
#pragma unroll
        for (int j = 0; j < 4; j++)
#pragma unroll
            for (int q = 0; q < 4; q++) c[i][j][q] = 0.f;

    uint4 rAh0 = *(const uint4*)(Ahi + a0off);
    uint4 rAh1 = *(const uint4*)(Ahi + a1off);
    uint4 rAl0 = *(const uint4*)(Alo + a0off);
    uint4 rAl1 = *(const uint4*)(Alo + a1off);
    uint4 rBh0 = *(const uint4*)(Whi + b0off);
    uint4 rBh1 = *(const uint4*)(Whi + b1off);
    uint4 rBl0 = *(const uint4*)(Wlo + b0off);
    uint4 rBl1 = *(const uint4*)(Wlo + b1off);

    const int nch = K >> 5;
    for (int ci = 0; ci < nch; ci++) {
        const int s = ci & 1;
        __nv_bfloat16* stg = gsm + s * 20480;      // 40960 bytes = 20480 bf16

        // STS current chunk from prefetch regs
        *(uint4*)(stg + s0) = rAh0;          *(uint4*)(stg + s1) = rAh1;
        *(uint4*)(stg + 5120 + s0) = rAl0;   *(uint4*)(stg + 5120 + s1) = rAl1;
        *(uint4*)(stg + 10240 + s0) = rBh0;  *(uint4*)(stg + 10240 + s1) = rBh1;
        *(uint4*)(stg + 15360 + s0) = rBl0;  *(uint4*)(stg + 15360 + s1) = rBl1;

        // LDG next chunk (full chunk of latency-hiding window ahead)
        if (ci + 1 < nch) {
            const int kn = (ci + 1) << 5;
            rAh0 = *(const uint4*)(Ahi + a0off + kn);
            rAh1 = *(const uint4*)(Ahi + a1off + kn);
            rAl0 = *(const uint4*)(Alo + a0off + kn);
            rAl1 = *(const uint4*)(Alo + a1off + kn);
            rBh0 = *(const uint4*)(Whi + b0off + kn);
            rBh1 = *(const uint4*)(Whi + b1off + kn);
            rBl0 = *(const uint4*)(Wlo + b0off + kn);
            rBl1 = *(const uint4*)(Wlo + b1off + kn);
        }

        __syncthreads();

        const uint32_t uAh = u_sm + s * 40960;
        const uint32_t uAl = uAh + 10240;
        const uint32_t uBh = uAh + 20480;
        const uint32_t uBl = uAh + 30720;

#pragma unroll
        for (int ks = 0; ks < 2; ks++) {
            uint32_t Ah[4][4], Al[4][4], Bh[4][2], Bl[4][2];
            const uint32_t ao = aoffL + ks * 32;
            const uint32_t bo = boffL + ks * 32;
#pragma unroll
            for (int mf = 0; mf < 4; mf++) {
                ldsm4(Ah[mf], uAh + ao + mf * (16 * 80));
                ldsm4(Al[mf], uAl + ao + mf * (16 * 80));
            }
#pragma unroll
            for (int p = 0; p < 2; p++) {
                uint32_t t[4];
                ldsm4(t, uBh + bo + p * (16 * 80));
                Bh[2*p][0] = t[0]; Bh[2*p][1] = t[1];
                Bh[2*p+1][0] = t[2]; Bh[2*p+1][1] = t[3];
                ldsm4(t, uBl + bo + p * (16 * 80));
                Bl[2*p][0] = t[0]; Bl[2*p][1] = t[1];
                Bl[2*p+1][0] = t[2]; Bl[2*p+1][1] = t[3];
            }
#pragma unroll
            for (int mf = 0; mf < 4; mf++) {
#pragma unroll
                for (int nf = 0; nf < 4; nf++) {
                    mma16816(c[mf][nf], Ah[mf], Bh[nf]);
                    mma16816(c[mf][nf], Ah[mf], Bl[nf]);
                    mma16816(c[mf][nf], Al[mf], Bh[nf]);
                }
            }
        }
    }

#pragma unroll
    for (int mf = 0; mf < 4; mf++) {
#pragma unroll
        for (int nf = 0; nf < 4; nf++) {
            const int mA = bm + m0 + mf * 16 + group;
            const int nA = bn + n0 + nf * 8 + tig * 2;
            float* p0 = C + (size_t)mA * N + nA;
            float* p1 = C + (size_t)(mA + 8) * N + nA;
            float v0 = c[mf][nf][0], v1 = c[mf][nf][1];
            float v2 = c[mf][nf][2], v3 = c[mf][nf][3];
            if (EPI == 1) {
                const float* bb = (bn < 3072) ? bias : bias2;
                const int nB = nA - ((bn < 3072) ? 0 : 3072);
                const float b0v = bb[nB], b1v = bb[nB + 1];
                v0 += b0v; v1 += b1v; v2 += b0v; v3 += b1v;
            } else if (EPI == 2) {
                const int ba = mA >> 10, sa = mA & 1023;
                const float* g0 = mod + (size_t)((ba << 7) + (sa >> 3)) * 6144 + 2048;
                const int bb2 = (mA + 8) >> 10, sb = (mA + 8) & 1023;
                const float* g1 = mod + (size_t)((bb2 << 7) + (sb >> 3)) * 6144 + 2048;
                v0 = res[(size_t)mA * N + nA]       + g0[nA]     * v0;
                v1 = res[(size_t)mA * N + nA + 1]   + g0[nA + 1] * v1;
                v2 = res[(size_t)(mA+8) * N + nA]   + g1[nA]     * v2;
                v3 = res[(size_t)(mA+8) * N + nA+1] + g1[nA + 1] * v3;
            }
            *(float2*)p0 = make_float2(v0, v1);
            *(float2*)p1 = make_float2(v2, v3);
        }
    }
}

// ---------------- merged weight split ----------------
struct WSegs {
    const float* src[9];
    int off[10];
};

__global__ __launch_bounds__(256) void wsplit_all_kernel(
    WSegs ws, __nv_bfloat16* __restrict__ hi, __nv_bfloat16* __restrict__ lo)
{
    const int base = blockIdx.x * 1024 + threadIdx.x * 4;
    int seg = 0;
#pragma unroll
    for (int k = 1; k < 9; k++) if (base >= ws.off[k]) seg = k;
    const float* src = ws.src[seg] + (base - ws.off[seg]);
    float4 v = *(const float4*)src;
    uint32_t h01, l01, h23, l23;
    split_pack2(v.x, v.y, h01, l01);
    split_pack2(v.z, v.w, h23, l23);
    *(uint2*)(hi + base) = make_uint2(h01, h23);
    *(uint2*)(lo + base) = make_uint2(l01, l23);
}

// ---------------- pointwise kernels ----------------
__global__ void silu_split_kernel(const float* __restrict__ in,
                                  __nv_bfloat16* __restrict__ hi,
                                  __nv_bfloat16* __restrict__ lo, int n)
{
    int i = blockIdx.x * blockDim.x + threadIdx.x;
    if (i >= n) return;
    __nv_bfloat16 h, l;
    split2(siluf(in[i]), h, l);
    hi[i] = h; lo[i] = l;
}

__global__ void swiglu_split_kernel(const float* __restrict__ FF,
                                    __nv_bfloat16* __restrict__ hi,
                                    __nv_bfloat16* __restrict__ lo)
{
    int i = blockIdx.x * blockDim.x + threadIdx.x;
    const int m = i >> 10, n = i & 1023;
    const float a  = FF[((size_t)m << 11) + n];
    const float b3 = FF[((size_t)m << 11) + 1024 + n];
    __nv_bfloat16 h, l;
    split2(siluf(a) * b3, h, l);
    hi[i] = h; lo[i] = l;
}

__global__ __launch_bounds__(256) void rmsnorm_mod_split_kernel(
    const float* __restrict__ X, const float* __restrict__ w,
    const float* __restrict__ mod, int seg,
    __nv_bfloat16* __restrict__ hi, __nv_bfloat16* __restrict__ lo)
{
    const int m = blockIdx.x;
    const float* x = X + (size_t)m * DIM;
    const int b = m >> 10;
    const int s = m & 1023;
    const float* md = mod + (size_t)((b << 7) + (s >> 3)) * 6144 + seg;
    const int tid = threadIdx.x;

    float v[4];
    float ss = 0.f;
#pragma unroll
    for (int i = 0; i < 4; i++) { v[i] = x[tid + 256 * i]; ss += v[i] * v[i]; }
#pragma unroll
    for (int off = 16; off; off >>= 1) ss += __shfl_xor_sync(0xffffffffu, ss, off);
    __shared__ float wsum[8];
    if ((tid & 31) == 0) wsum[tid >> 5] = ss;
    __syncthreads();
    float total = wsum[0] + wsum[1] + wsum[2] + wsum[3]
                + wsum[4] + wsum[5] + wsum[6] + wsum[7];
    const float inv = rsqrtf(total * (1.f / 1024.f) + 1e-6f);
#pragma unroll
    for (int i = 0; i < 4; i++) {
        const int n = tid + 256 * i;
        float y = v[i] * inv * w[n] * (1.f + md[1024 + n]) + md[n];
        __nv_bfloat16 h, l;
        split2(y, h, l);
        hi[(size_t)m * DIM + n] = h;
        lo[(size_t)m * DIM + n] = l;
    }
}

__global__ void rope_split_q_kernel(const float* __restrict__ QKV,
                                    const float* __restrict__ fc, const float* __restrict__ fs,
                                    __nv_bfloat16* __restrict__ Qhi, __nv_bfloat16* __restrict__ Qlo)
{
    const int idx = blockIdx.x * blockDim.x + threadIdx.x;
    const int m = idx >> 9;
    const int p = idx & 511;
    const int i = p & 31;
    const int s = m & 1023;
    const float cc = fc[s * 32 + i];
    const float sn = fs[s * 32 + i];
    const float* src = QKV + (size_t)m * 1536 + (p << 1);
    const float x1 = src[0], x2 = src[1];
    const float y1 = (x1 * cc - x2 * sn) * 0.125f;
    const float y2 = (x1 * sn + x2 * cc) * 0.125f;
    uint32_t h, l;
    split_pack2(y1, y2, h, l);
    ((uint32_t*)Qhi)[m * 512 + p] = h;
    ((uint32_t*)Qlo)[m * 512 + p] = l;
}

__global__ void rope_split_kv_kernel(const float* __restrict__ QKV,
                                     const float* __restrict__ fc, const float* __restrict__ fs,
                                     __nv_bfloat16* __restrict__ Khi, __nv_bfloat16* __restrict__ Klo,
                                     __nv_bfloat16* __restrict__ Vhi, __nv_bfloat16* __restrict__ Vlo)
{
    const int idx = blockIdx.x * blockDim.x + threadIdx.x;
    const int m = idx >> 7;
    const int p = idx & 127;
    const int i = p & 31;
    const int s = m & 1023;
    const float cc = fc[s * 32 + i];
    const float sn = fs[s * 32 + i];
    const float* srcK = QKV + (size_t)m * 1536 + 1024 + (p << 1);
    const float* srcV = QKV + (size_t)m * 1536 + 1280 + (p << 1);
    const float x1 = srcK[0], x2 = srcK[1];
    uint32_t h, l;
    split_pack2(x1 * cc - x2 * sn, x1 * sn + x2 * cc, h, l);
    ((uint32_t*)Khi)[m * 128 + p] = h;
    ((uint32_t*)Klo)[m * 128 + p] = l;
    split_pack2(srcV[0], srcV[1], h, l);
    ((uint32_t*)Vhi)[m * 128 + p] = h;
    ((uint32_t*)Vlo)[m * 128 + p] = l;
}

// ---------------- tensor-core split-bf16 flash attention (R7-proven) ----------------
#define AP 72
#define ATTN_SMEM 55296
__global__ __launch_bounds__(128) void attn_tc_kernel(
    const __nv_bfloat16* __restrict__ Qhi, const __nv_bfloat16* __restrict__ Qlo,
    const __nv_bfloat16* __restrict__ Khi, const __nv_bfloat16* __restrict__ Klo,
    const __nv_bfloat16* __restrict__ Vhi, const __nv_bfloat16* __restrict__ Vlo,
    __nv_bfloat16* __restrict__ Ohi, __nv_bfloat16* __restrict__ Olo)
{
    extern __shared__ __align__(16) __nv_bfloat16 sb[];
    __nv_bfloat16* Qh = sb;
    __nv_bfloat16* Ql = sb + 4608;
    __nv_bfloat16* Kh = sb + 9216;
    __nv_bfloat16* Kl = sb + 13824;
    __nv_bfloat16* Vh = sb + 18432;
    __nv_bfloat16* Vl = sb + 23040;

    const int qt = gridDim.x - 1 - blockIdx.x;
    const int h = blockIdx.y, b = blockIdx.z;
    const int kvh = h >> 2;
    const int tid = threadIdx.x, warp = tid >> 5, lane = tid & 31;
    const int q0 = qt << 6;

    for (int i = tid; i < 512; i += 128) {
        const int r = i >> 3, sg = (i & 7) * 8;
        const size_t g = (size_t)(b * SEQ + q0 + r) * DIM + h * HD + sg;
        *(uint4*)(Qh + r * AP + sg) = *(const uint4*)(Qhi + g);
        *(uint4*)(Ql + r * AP + sg) = *(const uint4*)(Qlo + g);
    }
    __syncthreads();

    const uint32_t uQh = (uint32_t)__cvta_generic_to_shared(Qh);
    const uint32_t uQl = (uint32_t)__cvta_generic_to_shared(Ql);
    uint32_t qh[4][4], ql[4][4];
    {
        const int qrow = warp * 16 + (lane & 15);
#pragma unroll
        for (int k = 0; k < 4; k++) {
            const uint32_t a = (uint32_t)((qrow * AP + k * 16 + (lane >> 4) * 8) * 2);
            ldsm4(qh[k], uQh + a);
            ldsm4(ql[k], uQl + a);
        }
    }

    const uint32_t uKh = (uint32_t)__cvta_generic_to_shared(Kh);
    const uint32_t uKl = (uint32_t)__cvta_generic_to_shared(Kl);
    const uint32_t uVh = (uint32_t)__cvta_generic_to_shared(Vh);
    const uint32_t uVl = (uint32_t)__cvta_generic_to_shared(Vl);
    const int krow = (lane & 7) + ((lane >> 4) & 1) * 8;
    const int kcol = ((lane >> 3) & 1) * 8;
    const int vrow = (lane & 7) + ((lane >> 3) & 1) * 8;
    const int vcol = ((lane >> 4) & 1) * 8;

    float o[8][4];
#pragma unroll
    for (int j = 0; j < 8; j++)
#pragma unroll
        for (int q = 0; q < 4; q++) o[j][q] = 0.f;
    float m0 = -1e30f, m1 = -1e30f, l0 = 0.f, l1 = 0.f;

    for (int t = 0; t <= qt; t++) {
        __syncthreads();
        for (int i = tid; i < 512; i += 128) {
            const int r = i >> 3, sg = (i & 7) * 8;
            const size_t g = (size_t)(b * SEQ + t * 64 + r) * 256 + kvh * 64 + sg;
            *(uint4*)(Kh + r * AP + sg) = *(const uint4*)(Khi + g);
            *(uint4*)(Kl + r * AP + sg) = *(const uint4*)(Klo + g);
            *(uint4*)(Vh + r * AP + sg) = *(const uint4*)(Vhi + g);
            *(uint4*)(Vl + r * AP + sg) = *(const uint4*)(Vlo + g);
        }
        __syncthreads();

        float sc[8][4];
#pragma unroll
        for (int j = 0; j < 8; j++)
#pragma unroll
            for (int q = 0; q < 4; q++) sc[j][q] = 0.f;
#pragma unroll
        for (int k = 0; k < 4; k++) {
            uint32_t bh[4][4], bl[4][4];
#pragma unroll
            for (int j2 = 0; j2 < 4; j2++) {
                const uint32_t a = (uint32_t)(((j2 * 16 + krow) * AP + k * 16 + kcol) * 2);
                ldsm4(bh[j2], uKh + a);
                ldsm4(bl[j2], uKl + a);
            }
#pragma unroll
            for (int j2 = 0; j2 < 4; j2++) {
                mma16816(sc[2*j2],   qh[k], &bh[j2][0]);
                mma16816(sc[2*j2],   qh[k], &bl[j2][0]);
                mma16816(sc[2*j2],   ql[k], &bh[j2][0]);
                mma16816(sc[2*j2+1], qh[k], &bh[j2][2]);
                mma16816(sc[2*j2+1], qh[k], &bl[j2][2]);
                mma16816(sc[2*j2+1], ql[k], &bh[j2][2]);
            }
        }

        if (t == qt) {
            const int rb0 = warp * 2;
#pragma unroll
            for (int j = 0; j < 8; j++) {
                if (j > rb0)     { sc[j][0] = -1e30f; sc[j][1] = -1e30f; }
                if (j > rb0 + 1) { sc[j][2] = -1e30f; sc[j][3] = -1e30f; }
            }
        }

        float mx0 = -1e30f, mx1 = -1e30f;
#pragma unroll
        for (int j = 0; j < 8; j++) {
            mx0 = fmaxf(mx0, fmaxf(sc[j][0], sc[j][1]));
            mx1 = fmaxf(mx1, fmaxf(sc[j][2], sc[j][3]));
        }
        mx0 = fmaxf(mx0, __shfl_xor_sync(0xffffffffu, mx0, 1));
        mx0 = fmaxf(mx0, __shfl_xor_sync(0xffffffffu, mx0, 2));
        mx1 = fmaxf(mx1, __shfl_xor_sync(0xffffffffu, mx1, 1));
        mx1 = fmaxf(mx1, __shfl_xor_sync(0xffffffffu, mx1, 2));
        const float mn0 = fmaxf(m0, mx0);
        const float mn1 = fmaxf(m1, mx1);
        const float cr0 = __expf(m0 - mn0);
        const float cr1 = __expf(m1 - mn1);
        float ps0 = 0.f, ps1 = 0.f;
#pragma unroll
        for (int j = 0; j < 8; j++) {
            sc[j][0] = __expf(sc[j][0] - mn0);
            sc[j][1] = __expf(sc[j][1] - mn0);
            sc[j][2] = __expf(sc[j][2] - mn1);
            sc[j][3] = __expf(sc[j][3] - mn1);
            ps0 += sc[j][0] + sc[j][1];
            ps1 += sc[j][2] + sc[j][3];
        }
        ps0 += __shfl_xor_sync(0xffffffffu, ps0, 1);
        ps0 += __shfl_xor_sync(0xffffffffu, ps0, 2);
        ps1 += __shfl_xor_sync(0xffffffffu, ps1, 1);
        ps1 += __shfl_xor_sync(0xffffffffu, ps1, 2);
        l0 = l0 * cr0 + ps0;  m0 = mn0;
        l1 = l1 * cr1 + ps1;  m1 = mn1;
#pragma unroll
        for (int j = 0; j < 8; j++) {
            o[j][0] *= cr0; o[j][1] *= cr0;
            o[j][2] *= cr1; o[j][3] *= cr1;
        }

        uint32_t pH[4][4], pL[4][4];
#pragma unroll
        for (int tt = 0; tt < 4; tt++) {
            split_pack2(sc[2*tt][0],   sc[2*tt][1],   pH[tt][0], pL[tt][0]);
            split_pack2(sc[2*tt][2],   sc[2*tt][3],   pH[tt][1], pL[tt][1]);
            split_pack2(sc[2*tt+1][0], sc[2*tt+1][1], pH[tt][2], pL[tt][2]);
            split_pack2(sc[2*tt+1][2], sc[2*tt+1][3], pH[tt][3], pL[tt][3]);
        }

#pragma unroll
        for (int tt = 0; tt < 4; tt++) {
#pragma unroll
            for (int j2 = 0; j2 < 4; j2++) {
                uint32_t vh4[4], vl4[4];
                const uint32_t a = (uint32_t)(((tt * 16 + vrow) * AP + j2 * 16 + vcol) * 2);
                ldsm4t(vh4, uVh + a);
                ldsm4t(vl4, uVl + a);
                mma16816(o[2*j2],   pH[tt], &vh4[0]);
                mma16816(o[2*j2],   pH[tt], &vl4[0]);
                mma16816(o[2*j2],   pL[tt], &vh4[0]);
                mma16816(o[2*j2+1], pH[tt], &vh4[2]);
                mma16816(o[2*j2+1], pH[tt], &vl4[2]);
                mma16816(o[2*j2+1], pL[tt], &vh4[2]);
            }
        }
    }

    const float inv0 = 1.f / l0;
    const float inv1 = 1.f / l1;
    const size_t row0 = (size_t)(b * SEQ + q0 + warp * 16 + (lane >> 2));
    const size_t row1 = row0 + 8;
#pragma unroll
    for (int j = 0; j < 8; j++) {
        const int col = h * HD + j * 8 + (lane & 3) * 2;
        __nv_bfloat16 hh, ll;
        split2(o[j][0] * inv0, hh, ll); Ohi[row0 * DIM + col]     = hh; Olo[row0 * DIM + col]     = ll;
        split2(o[j][1] * inv0, hh, ll); Ohi[row0 * DIM + col + 1] = hh; Olo[row0 * DIM + col + 1] = ll;
        split2(o[j][2] * inv1, hh, ll); Ohi[row1 * DIM + col]     = hh; Olo[row1 * DIM + col]     = ll;
        split2(o[j][3] * inv1, hh, ll); Ohi[row1 * DIM + col + 1] = hh; Olo[row1 * DIM + col + 1] = ll;
    }
}

// ---------------- launch ----------------
extern "C" void kernel_launch(void* const* d_in, const int* in_sizes, int n_in,
                              void* d_out, int out_size)
{
    const float* x   = (const float*)d_in[0];
    const float* vec = (const float*)d_in[1];
    const float* wq  = (const float*)d_in[2];
    const float* wk  = (const float*)d_in[3];
    const float* wv  = (const float*)d_in[4];
    const float* wo  = (const float*)d_in[5];
    const float* w1  = (const float*)d_in[6];
    const float* w2  = (const float*)d_in[7];
    const float* w3  = (const float*)d_in[8];
    const float* maw = (const float*)d_in[9];
    const float* mab = (const float*)d_in[10];
    const float* mfw = (const float*)d_in[11];
    const float* mfb = (const float*)d_in[12];
    const float* n1w = (const float*)d_in[13];
    const float* n2w = (const float*)d_in[14];
    const float* fc  = (const float*)d_in[15];
    const float* fs  = (const float*)d_in[16];
    float* out = (float*)d_out;

    __nv_bfloat16 *Whi, *Wlo, *SVhi, *SVlo, *XNhi, *XNlo, *AOhi, *AOlo, *HNhi, *HNlo, *G1hi, *G1lo;
    __nv_bfloat16 *Qhi, *Qlo, *Khi, *Klo, *Vhi, *Vlo;
    float *MOD, *QKV, *FF, *H;
    cudaGetSymbolAddress((void**)&Whi,  g_Whi);
    cudaGetSymbolAddress((void**)&Wlo,  g_Wlo);
    cudaGetSymbolAddress((void**)&SVhi, g_SVhi);
    cudaGetSymbolAddress((void**)&SVlo, g_SVlo);
    cudaGetSymbolAddress((void**)&XNhi, g_XNhi);
    cudaGetSymbolAddress((void**)&XNlo, g_XNlo);
    cudaGetSymbolAddress((void**)&AOhi, g_AOhi);
    cudaGetSymbolAddress((void**)&AOlo, g_AOlo);
    cudaGetSymbolAddress((void**)&HNhi, g_HNhi);
    cudaGetSymbolAddress((void**)&HNlo, g_HNlo);
    cudaGetSymbolAddress((void**)&G1hi, g_G1hi);
    cudaGetSymbolAddress((void**)&G1lo, g_G1lo);
    cudaGetSymbolAddress((void**)&Qhi,  g_Qhi);
    cudaGetSymbolAddress((void**)&Qlo,  g_Qlo);
    cudaGetSymbolAddress((void**)&Khi,  g_Khi);
    cudaGetSymbolAddress((void**)&Klo,  g_Klo);
    cudaGetSymbolAddress((void**)&Vhi,  g_Vhi);
    cudaGetSymbolAddress((void**)&Vlo,  g_Vlo);
    cudaGetSymbolAddress((void**)&MOD,  g_MOD);
    cudaGetSymbolAddress((void**)&QKV,  g_QKV);
    cudaGetSymbolAddress((void**)&FF,   g_FF);
    cudaGetSymbolAddress((void**)&H,    g_H);

    cudaFuncSetAttribute(attn_tc_kernel, cudaFuncAttributeMaxDynamicSharedMemorySize, ATTN_SMEM);
    cudaFuncSetAttribute(hgemm_kernel<0>, cudaFuncAttributeMaxDynamicSharedMemorySize, GEMM_SMEM);
    cudaFuncSetAttribute(hgemm_kernel<1>, cudaFuncAttributeMaxDynamicSharedMemorySize, GEMM_SMEM);
    cudaFuncSetAttribute(hgemm_kernel<2>, cudaFuncAttributeMaxDynamicSharedMemorySize, GEMM_SMEM);

    // 0) split all weights (one launch)
    WSegs ws;
    ws.src[0]=wq; ws.src[1]=wk; ws.src[2]=wv; ws.src[3]=wo; ws.src[4]=w1;
    ws.src[5]=w3; ws.src[6]=w2; ws.src[7]=maw; ws.src[8]=mfw;
    ws.off[0]=OFF_WQ;  ws.off[1]=OFF_WK;  ws.off[2]=OFF_WV;  ws.off[3]=OFF_WO;
    ws.off[4]=OFF_W1;  ws.off[5]=OFF_W3;  ws.off[6]=OFF_W2;  ws.off[7]=OFF_MAW;
    ws.off[8]=OFF_MFW; ws.off[9]=WTOTAL;
    wsplit_all_kernel<<<WTOTAL/1024, 256>>>(ws, Whi, Wlo);

    // 1) modulation: merged GEMM, N = 6144
    silu_split_kernel<<<(MODROWS*DIM + 255)/256, 256>>>(vec, SVhi, SVlo, MODROWS*DIM);
    hgemm_kernel<1><<<dim3(48, 4), 256, GEMM_SMEM>>>(SVhi, SVlo, Whi+OFF_MAW, Wlo+OFF_MAW, MOD,
                                                     MODROWS, 6144, DIM, mab, mfb, nullptr, nullptr);

    // 2) xn
    rmsnorm_mod_split_kernel<<<MROWS, 256>>>(x, n1w, MOD, 0, XNhi, XNlo);

    // 3) merged QKV projection, N = 1536
    hgemm_kernel<0><<<dim3(12, 32), 256, GEMM_SMEM>>>(XNhi, XNlo, Whi+OFF_WQ, Wlo+OFF_WQ, QKV,
                                                      MROWS, 1536, DIM, nullptr, nullptr, nullptr, nullptr);

    // 4) rope + split
    rope_split_q_kernel <<<(MROWS*512)/256, 256>>>(QKV, fc, fs, Qhi, Qlo);
    rope_split_kv_kernel<<<(MROWS*128)/256, 256>>>(QKV, fc, fs, Khi, Klo, Vhi, Vlo);

    // 5) attention
    attn_tc_kernel<<<dim3(16, 16, 4), 128, ATTN_SMEM>>>(Qhi, Qlo, Khi, Klo, Vhi, Vlo, AOhi, AOlo);

    // 6) h = x + gate_a * (AO @ wo^T)
    hgemm_kernel<2><<<dim3(8, 32), 256, GEMM_SMEM>>>(AOhi, AOlo, Whi+OFF_WO, Wlo+OFF_WO, H,
                                                     MROWS, DIM, DIM, nullptr, nullptr, x, MOD);

    // 7) hn
    rmsnorm_mod_split_kernel<<<MROWS, 256>>>(H, n2w, MOD, 3072, HNhi, HNlo);

    // 8) FFN
    hgemm_kernel<0><<<dim3(16, 32), 256, GEMM_SMEM>>>(HNhi, HNlo, Whi+OFF_W1, Wlo+OFF_W1, FF,
                                                      MROWS, 2048, DIM, nullptr, nullptr, nullptr, nullptr);
    swiglu_split_kernel<<<(MROWS*DIM)/256, 256>>>(FF, G1hi, G1lo);
    hgemm_kernel<2><<<dim3(8, 32), 256, GEMM_SMEM>>>(G1hi, G1lo, Whi+OFF_W2, Wlo+OFF_W2, out,
                                                     MROWS, DIM, DIM, nullptr, nullptr, H, MOD + 3072);
}